// round 1
// baseline (speedup 1.0000x reference)
#include <cuda_runtime.h>
#include <math.h>

// Problem constants
#define BATCH 4
#define SEQ   1024
#define DIM   1024
#define NHEAD 16
#define DK    64          // DIM / NHEAD
#define MROWS (BATCH * SEQ)   // 4096
#define LN_EPS 1e-5f

// ---------------- scratch (device globals: no allocs allowed) ----------------
__device__ float g_q[(size_t)MROWS * DIM];
__device__ float g_k[(size_t)MROWS * DIM];
__device__ float g_v[(size_t)MROWS * DIM];
__device__ float g_ctx[(size_t)MROWS * DIM];
__device__ float g_outb[(size_t)MROWS * DIM];
__device__ float g_scores[(size_t)BATCH * NHEAD * SEQ * SEQ]; // 256 MB

// ---------------- generic GEMM: Y[M,N] = X[M,K] @ W[N,K]^T + bias[N] --------
// Tiles: BM=BN=64, BK=16, thread tile 4x4, 256 threads.
#define GBM 64
#define GBN 64
#define GBK 16

__global__ __launch_bounds__(256)
void gemm_bias_kernel(const float* __restrict__ A,
                      const float* __restrict__ W,
                      const float* __restrict__ bias,
                      float* __restrict__ Y,
                      int M, int N, int K)
{
    __shared__ float As[GBK][GBM + 1];
    __shared__ float Bs[GBK][GBN + 1];

    const int tid = threadIdx.x;
    const int bm = blockIdx.y * GBM;
    const int bn = blockIdx.x * GBN;
    const int tm = (tid / 16) * 4;
    const int tn = (tid % 16) * 4;

    float acc[4][4];
#pragma unroll
    for (int i = 0; i < 4; i++)
#pragma unroll
        for (int j = 0; j < 4; j++) acc[i][j] = 0.f;

    for (int k0 = 0; k0 < K; k0 += GBK) {
        // load 64x16 A tile and 64x16 W tile (4 elems each per thread)
#pragma unroll
        for (int i = 0; i < 4; i++) {
            int idx = tid + i * 256;
            int r = idx / GBK, c = idx % GBK;
            As[c][r] = A[(size_t)(bm + r) * K + k0 + c];
            Bs[c][r] = W[(size_t)(bn + r) * K + k0 + c];
        }
        __syncthreads();
#pragma unroll
        for (int kk = 0; kk < GBK; kk++) {
            float a[4], b[4];
#pragma unroll
            for (int i = 0; i < 4; i++) a[i] = As[kk][tm + i];
#pragma unroll
            for (int j = 0; j < 4; j++) b[j] = Bs[kk][tn + j];
#pragma unroll
            for (int i = 0; i < 4; i++)
#pragma unroll
                for (int j = 0; j < 4; j++) acc[i][j] += a[i] * b[j];
        }
        __syncthreads();
    }

#pragma unroll
    for (int i = 0; i < 4; i++) {
        size_t row = (size_t)(bm + tm + i) * N;
#pragma unroll
        for (int j = 0; j < 4; j++) {
            int n = bn + tn + j;
            Y[row + n] = acc[i][j] + bias[n];
        }
    }
}

// ---------------- scores: for each (b,h): S[m,n] = (q_m . k_n) / 8 ----------
__global__ __launch_bounds__(256)
void scores_kernel(const float* __restrict__ q,
                   const float* __restrict__ k,
                   float* __restrict__ scores)
{
    const int bh = blockIdx.z;             // 0..63
    const int b = bh / NHEAD;
    const int h = bh % NHEAD;
    const int bm = blockIdx.y * 64;
    const int bn = blockIdx.x * 64;

    const float* qb = q + (size_t)b * SEQ * DIM + h * DK;
    const float* kb = k + (size_t)b * SEQ * DIM + h * DK;

    __shared__ float qs[64][DK + 1];
    __shared__ float ks[64][DK + 1];

    const int tid = threadIdx.x;
    // load 64x64 of each (16 elems per thread)
#pragma unroll
    for (int i = 0; i < 16; i++) {
        int idx = tid + i * 256;
        int r = idx / DK, c = idx % DK;
        qs[r][c] = qb[(size_t)(bm + r) * DIM + c];
        ks[r][c] = kb[(size_t)(bn + r) * DIM + c];
    }
    __syncthreads();

    const int tm = (tid / 16) * 4;
    const int tn = (tid % 16) * 4;

    float acc[4][4];
#pragma unroll
    for (int i = 0; i < 4; i++)
#pragma unroll
        for (int j = 0; j < 4; j++) acc[i][j] = 0.f;

#pragma unroll
    for (int kk = 0; kk < DK; kk++) {
        float a[4], bb[4];
#pragma unroll
        for (int i = 0; i < 4; i++) a[i] = qs[tm + i][kk];
#pragma unroll
        for (int j = 0; j < 4; j++) bb[j] = ks[tn + j][kk];
#pragma unroll
        for (int i = 0; i < 4; i++)
#pragma unroll
            for (int j = 0; j < 4; j++) acc[i][j] += a[i] * bb[j];
    }

    float* sp = scores + (size_t)bh * SEQ * SEQ;
#pragma unroll
    for (int i = 0; i < 4; i++) {
        size_t row = (size_t)(bm + tm + i) * SEQ;
#pragma unroll
        for (int j = 0; j < 4; j++)
            sp[row + bn + tn + j] = acc[i][j] * 0.125f;   // 1/sqrt(64)
    }
}

// ---------------- double softmax over each row of scores --------------------
__global__ __launch_bounds__(256)
void softmax2_kernel(float* __restrict__ scores)
{
    __shared__ float row[SEQ];
    __shared__ float red[256];

    const size_t r = blockIdx.x;            // 0 .. 65535
    float* p = scores + r * SEQ;
    const int tid = threadIdx.x;

    for (int i = tid; i < SEQ; i += 256) row[i] = p[i];
    __syncthreads();

#pragma unroll
    for (int pass = 0; pass < 2; pass++) {
        // max
        float m = -INFINITY;
        for (int i = tid; i < SEQ; i += 256) m = fmaxf(m, row[i]);
        red[tid] = m; __syncthreads();
        for (int s = 128; s > 0; s >>= 1) {
            if (tid < s) red[tid] = fmaxf(red[tid], red[tid + s]);
            __syncthreads();
        }
        m = red[0]; __syncthreads();
        // exp + sum
        float sum = 0.f;
        for (int i = tid; i < SEQ; i += 256) {
            float e = __expf(row[i] - m);
            row[i] = e;
            sum += e;
        }
        red[tid] = sum; __syncthreads();
        for (int s = 128; s > 0; s >>= 1) {
            if (tid < s) red[tid] += red[tid + s];
            __syncthreads();
        }
        float inv = 1.0f / red[0]; __syncthreads();
        for (int i = tid; i < SEQ; i += 256) row[i] *= inv;
        __syncthreads();
    }

    for (int i = tid; i < SEQ; i += 256) p[i] = row[i];
}

// ---------------- ctx: for each (b,h): C[m,d] = sum_s attn[m,s] v[s,d] ------
#define CBK 32
__global__ __launch_bounds__(256)
void ctx_kernel(const float* __restrict__ scores,
                const float* __restrict__ v,
                float* __restrict__ ctx)
{
    const int bh = blockIdx.z;
    const int b = bh / NHEAD;
    const int h = bh % NHEAD;
    const int bm = blockIdx.y * 64;

    const float* ap = scores + (size_t)bh * SEQ * SEQ;
    const float* vb = v + (size_t)b * SEQ * DIM + h * DK;

    __shared__ float As[64][CBK + 1];
    __shared__ float Vs[CBK][DK + 1];

    const int tid = threadIdx.x;
    const int tm = (tid / 16) * 4;
    const int tn = (tid % 16) * 4;

    float acc[4][4];
#pragma unroll
    for (int i = 0; i < 4; i++)
#pragma unroll
        for (int j = 0; j < 4; j++) acc[i][j] = 0.f;

    for (int s0 = 0; s0 < SEQ; s0 += CBK) {
        // load attn tile 64x32 (8/thread) and v tile 32x64 (8/thread)
#pragma unroll
        for (int i = 0; i < 8; i++) {
            int idx = tid + i * 256;
            int r = idx / CBK, c = idx % CBK;
            As[r][c] = ap[(size_t)(bm + r) * SEQ + s0 + c];
            int vr = idx / DK, vc = idx % DK;
            Vs[vr][vc] = vb[(size_t)(s0 + vr) * DIM + vc];
        }
        __syncthreads();
#pragma unroll
        for (int kk = 0; kk < CBK; kk++) {
            float a[4], bb[4];
#pragma unroll
            for (int i = 0; i < 4; i++) a[i] = As[tm + i][kk];
#pragma unroll
            for (int j = 0; j < 4; j++) bb[j] = Vs[kk][tn + j];
#pragma unroll
            for (int i = 0; i < 4; i++)
#pragma unroll
                for (int j = 0; j < 4; j++) acc[i][j] += a[i] * bb[j];
        }
        __syncthreads();
    }

    float* cp = ctx + (size_t)b * SEQ * DIM + h * DK;
#pragma unroll
    for (int i = 0; i < 4; i++) {
        size_t row = (size_t)(bm + tm + i) * DIM;
#pragma unroll
        for (int j = 0; j < 4; j++)
            cp[row + tn + j] = acc[i][j];
    }
}

// ---------------- residual + layernorm --------------------------------------
__global__ __launch_bounds__(256)
void ln_kernel(const float* __restrict__ proj,
               const float* __restrict__ Qres,
               const float* __restrict__ g,
               const float* __restrict__ bta,
               float* __restrict__ out)
{
    __shared__ float red[256];
    const size_t row = blockIdx.x;        // 0..4095
    const float* x1 = proj + row * DIM;
    const float* x2 = Qres + row * DIM;
    const int tid = threadIdx.x;

    float vals[4];
    float sum = 0.f;
#pragma unroll
    for (int j = 0; j < 4; j++) {
        int i = tid + j * 256;
        vals[j] = x1[i] + x2[i];
        sum += vals[j];
    }
    red[tid] = sum; __syncthreads();
    for (int s = 128; s > 0; s >>= 1) {
        if (tid < s) red[tid] += red[tid + s];
        __syncthreads();
    }
    float mu = red[0] / DIM; __syncthreads();

    float sq = 0.f;
#pragma unroll
    for (int j = 0; j < 4; j++) {
        float d = vals[j] - mu;
        sq += d * d;
    }
    red[tid] = sq; __syncthreads();
    for (int s = 128; s > 0; s >>= 1) {
        if (tid < s) red[tid] += red[tid + s];
        __syncthreads();
    }
    float rstd = rsqrtf(red[0] / DIM + LN_EPS);

    float* op = out + row * DIM;
#pragma unroll
    for (int j = 0; j < 4; j++) {
        int i = tid + j * 256;
        op[i] = (vals[j] - mu) * rstd * g[i] + bta[i];
    }
}

// ---------------- launch -----------------------------------------------------
extern "C" void kernel_launch(void* const* d_in, const int* in_sizes, int n_in,
                              void* d_out, int out_size)
{
    const float* Q   = (const float*)d_in[0];
    const float* K   = (const float*)d_in[1];
    const float* V   = (const float*)d_in[2];
    const float* Wq  = (const float*)d_in[3];
    const float* bq  = (const float*)d_in[4];
    const float* Wk  = (const float*)d_in[5];
    const float* bk  = (const float*)d_in[6];
    const float* Wv  = (const float*)d_in[7];
    const float* bv  = (const float*)d_in[8];
    const float* Wo  = (const float*)d_in[9];
    const float* bo  = (const float*)d_in[10];
    const float* lng = (const float*)d_in[11];
    const float* lnb = (const float*)d_in[12];
    float* out = (float*)d_out;

    float *q, *k, *v, *ctx, *outb, *scores;
    cudaGetSymbolAddress((void**)&q,      g_q);
    cudaGetSymbolAddress((void**)&k,      g_k);
    cudaGetSymbolAddress((void**)&v,      g_v);
    cudaGetSymbolAddress((void**)&ctx,    g_ctx);
    cudaGetSymbolAddress((void**)&outb,   g_outb);
    cudaGetSymbolAddress((void**)&scores, g_scores);

    dim3 gproj(DIM / GBN, MROWS / GBM);     // (16, 64)
    gemm_bias_kernel<<<gproj, 256>>>(Q, Wq, bq, q, MROWS, DIM, DIM);
    gemm_bias_kernel<<<gproj, 256>>>(K, Wk, bk, k, MROWS, DIM, DIM);
    gemm_bias_kernel<<<gproj, 256>>>(V, Wv, bv, v, MROWS, DIM, DIM);

    dim3 gsc(SEQ / 64, SEQ / 64, BATCH * NHEAD);   // (16,16,64)
    scores_kernel<<<gsc, 256>>>(q, k, scores);

    softmax2_kernel<<<BATCH * NHEAD * SEQ, 256>>>(scores);

    dim3 gctx(1, SEQ / 64, BATCH * NHEAD);         // (1,16,64)
    ctx_kernel<<<gctx, 256>>>(scores, v, ctx);

    gemm_bias_kernel<<<gproj, 256>>>(ctx, Wo, bo, outb, MROWS, DIM, DIM);

    ln_kernel<<<MROWS, 256>>>(outb, Q, lng, lnb, out);
}

// round 3
// speedup vs baseline: 1.7804x; 1.7804x over previous
#include <cuda_runtime.h>
#include <cuda_bf16.h>
#include <cstdint>
#include <math.h>

// Problem constants
#define BATCH 4
#define SEQ   1024
#define DIM   1024
#define NHEAD 16
#define DK    64
#define MROWS (BATCH * SEQ)   // 4096
#define LN_EPS 1e-5f

// ---------------- scratch (device globals: no allocs allowed) ----------------
__device__ float g_q[(size_t)MROWS * DIM];
__device__ float g_k[(size_t)MROWS * DIM];
__device__ float g_v[(size_t)MROWS * DIM];
__device__ float g_ctx[(size_t)MROWS * DIM];
__device__ float g_outb[(size_t)MROWS * DIM];
__device__ float g_scores[(size_t)BATCH * NHEAD * SEQ * SEQ]; // 256 MB
// bf16 hi/lo staging for tensor-core GEMMs
__device__ __nv_bfloat16 g_a_hi[(size_t)MROWS * DIM];
__device__ __nv_bfloat16 g_a_lo[(size_t)MROWS * DIM];
__device__ __nv_bfloat16 g_w_hi[(size_t)DIM * DIM];
__device__ __nv_bfloat16 g_w_lo[(size_t)DIM * DIM];

// =================== baseline-PTX helpers (no 'a'-suffix features) ===========
__device__ __forceinline__ uint32_t s2u(const void* p) {
    uint32_t a;
    asm("{ .reg .u64 t; cvta.to.shared.u64 t, %1; cvt.u32.u64 %0, t; }"
        : "=r"(a) : "l"(p));
    return a;
}

__device__ __forceinline__ void cp16(uint32_t dst, const void* src) {
    asm volatile("cp.async.cg.shared.global [%0], [%1], 16;"
                 :: "r"(dst), "l"(src) : "memory");
}
__device__ __forceinline__ void cp_commit() {
    asm volatile("cp.async.commit_group;" ::: "memory");
}
template <int N>
__device__ __forceinline__ void cp_wait() {
    asm volatile("cp.async.wait_group %0;" :: "n"(N) : "memory");
}

__device__ __forceinline__ void ldsm4(uint32_t& r0, uint32_t& r1,
                                      uint32_t& r2, uint32_t& r3, uint32_t a) {
    asm volatile("ldmatrix.sync.aligned.m8n8.x4.shared.b16 {%0,%1,%2,%3}, [%4];"
                 : "=r"(r0), "=r"(r1), "=r"(r2), "=r"(r3) : "r"(a));
}

__device__ __forceinline__ void mma16816(float* c, const uint32_t* a,
                                         const uint32_t* b) {
    asm volatile("mma.sync.aligned.m16n8k16.row.col.f32.bf16.bf16.f32 "
                 "{%0,%1,%2,%3}, {%4,%5,%6,%7}, {%8,%9}, {%0,%1,%2,%3};"
                 : "+f"(c[0]), "+f"(c[1]), "+f"(c[2]), "+f"(c[3])
                 : "r"(a[0]), "r"(a[1]), "r"(a[2]), "r"(a[3]),
                   "r"(b[0]), "r"(b[1]));
}

// =================== fp32 -> bf16 hi/lo split conversion =====================
__global__ __launch_bounds__(256)
void cvt_hilo_kernel(const float* __restrict__ x,
                     __nv_bfloat16* __restrict__ hi,
                     __nv_bfloat16* __restrict__ lo,
                     int n4)
{
    int i = blockIdx.x * blockDim.x + threadIdx.x;
    if (i >= n4) return;
    float4 v = ((const float4*)x)[i];
    __nv_bfloat16 h0 = __float2bfloat16(v.x);
    __nv_bfloat16 h1 = __float2bfloat16(v.y);
    __nv_bfloat16 h2 = __float2bfloat16(v.z);
    __nv_bfloat16 h3 = __float2bfloat16(v.w);
    __nv_bfloat16 l0 = __float2bfloat16(v.x - __bfloat162float(h0));
    __nv_bfloat16 l1 = __float2bfloat16(v.y - __bfloat162float(h1));
    __nv_bfloat16 l2 = __float2bfloat16(v.z - __bfloat162float(h2));
    __nv_bfloat16 l3 = __float2bfloat16(v.w - __bfloat162float(h3));
    ((__nv_bfloat162*)hi)[2 * i]     = __nv_bfloat162(h0, h1);
    ((__nv_bfloat162*)hi)[2 * i + 1] = __nv_bfloat162(h2, h3);
    ((__nv_bfloat162*)lo)[2 * i]     = __nv_bfloat162(l0, l1);
    ((__nv_bfloat162*)lo)[2 * i + 1] = __nv_bfloat162(l2, l3);
}

// =================== mma.sync GEMM: Y[M,N] = A @ W^T + bias ==================
// CTA 128x128, BK=64, 2-stage cp.async pipeline, bf16x3 split accumulation.
// 8 warps in 4x2; warp tile 32(m) x 64(n); m16n8k16 fragments via ldmatrix.
#define TCG_STAGE 65536            // 4 sub-tiles (Ahi,Alo,Bhi,Blo) x 16KB
#define TCG_SMEM  (2 * TCG_STAGE)  // 128KB

// swizzled byte offset within a 128row x 64col bf16 tile (128B rows)
__device__ __forceinline__ uint32_t tile_off(int row, int chunk) {
    return (uint32_t)(row * 128 + ((chunk ^ (row & 7)) << 4));
}

__global__ __launch_bounds__(256)
void tc_gemm_kernel(const __nv_bfloat16* __restrict__ Ahi,
                    const __nv_bfloat16* __restrict__ Alo,
                    const __nv_bfloat16* __restrict__ Bhi,
                    const __nv_bfloat16* __restrict__ Blo,
                    const float* __restrict__ bias,
                    float* __restrict__ Y)
{
    extern __shared__ char tsm[];
    const int tid = threadIdx.x;
    const int wid = tid >> 5;
    const int lane = tid & 31;
    const int wm = wid >> 1;          // 0..3
    const int wn = wid & 1;           // 0..1
    const int bm = blockIdx.y * 128;
    const int bn = blockIdx.x * 128;
    const uint32_t sbase = s2u(tsm);

    float acc[2][8][4];
#pragma unroll
    for (int i = 0; i < 2; i++)
#pragma unroll
        for (int j = 0; j < 8; j++)
#pragma unroll
            for (int r = 0; r < 4; r++) acc[i][j][r] = 0.f;

    // async load of K-tile kt into stage s
    auto load_stage = [&](int kt, int s) {
        const uint32_t stage = sbase + s * TCG_STAGE;
#pragma unroll
        for (int i = 0; i < 16; i++) {
            int u = tid + i * 256;
            int sub = u >> 10;          // 0=Ahi 1=Alo 2=Bhi 3=Blo
            int idx = u & 1023;
            int row = idx >> 3;
            int c = idx & 7;
            const __nv_bfloat16* src =
                (sub == 0) ? Ahi + (size_t)(bm + row) * DIM
              : (sub == 1) ? Alo + (size_t)(bm + row) * DIM
              : (sub == 2) ? Bhi + (size_t)(bn + row) * DIM
                           : Blo + (size_t)(bn + row) * DIM;
            cp16(stage + sub * 16384 + tile_off(row, c), src + kt * 64 + c * 8);
        }
        cp_commit();
    };

    load_stage(0, 0);

    for (int kt = 0; kt < 16; kt++) {
        if (kt < 15) load_stage(kt + 1, (kt + 1) & 1);
        if (kt < 15) cp_wait<1>(); else cp_wait<0>();
        __syncthreads();

        const uint32_t st = sbase + (kt & 1) * TCG_STAGE;
#pragma unroll
        for (int ks = 0; ks < 4; ks++) {
            // A fragments (2 m-tiles, hi & lo)
            uint32_t ahi[2][4], alo[2][4];
#pragma unroll
            for (int mt = 0; mt < 2; mt++) {
                int row = wm * 32 + mt * 16 + (lane & 15);
                int chunk = ks * 2 + (lane >> 4);
                uint32_t a0 = st + tile_off(row, chunk);
                ldsm4(ahi[mt][0], ahi[mt][1], ahi[mt][2], ahi[mt][3], a0);
                ldsm4(alo[mt][0], alo[mt][1], alo[mt][2], alo[mt][3], a0 + 16384);
            }
            // B fragments (4 pairs of n-tiles, hi & lo)
            uint32_t bh[4][4], bl[4][4];
#pragma unroll
            for (int p = 0; p < 4; p++) {
                int n = wn * 64 + p * 16 + ((lane >> 4) << 3) + (lane & 7);
                int chunk = ks * 2 + ((lane >> 3) & 1);
                uint32_t a0 = st + 32768 + tile_off(n, chunk);
                ldsm4(bh[p][0], bh[p][1], bh[p][2], bh[p][3], a0);
                ldsm4(bl[p][0], bl[p][1], bl[p][2], bl[p][3], a0 + 16384);
            }
            // MMAs: acc += Ahi*Bhi + Ahi*Blo + Alo*Bhi
#pragma unroll
            for (int mt = 0; mt < 2; mt++)
#pragma unroll
                for (int nt = 0; nt < 8; nt++) {
                    const uint32_t* bhp = &bh[nt >> 1][(nt & 1) * 2];
                    const uint32_t* blp = &bl[nt >> 1][(nt & 1) * 2];
                    mma16816(acc[mt][nt], ahi[mt], bhp);
                    mma16816(acc[mt][nt], ahi[mt], blp);
                    mma16816(acc[mt][nt], alo[mt], bhp);
                }
        }
        __syncthreads();
    }

    // epilogue: registers -> gmem (+bias), float2 stores
    const int gq = lane >> 2;        // 0..7
    const int tq = lane & 3;         // 0..3
#pragma unroll
    for (int mt = 0; mt < 2; mt++) {
#pragma unroll
        for (int nt = 0; nt < 8; nt++) {
            int col = bn + wn * 64 + nt * 8 + tq * 2;
            float bx = bias[col], by = bias[col + 1];
            int r0 = bm + wm * 32 + mt * 16 + gq;
            float2 v0 = make_float2(acc[mt][nt][0] + bx, acc[mt][nt][1] + by);
            float2 v1 = make_float2(acc[mt][nt][2] + bx, acc[mt][nt][3] + by);
            *(float2*)(Y + (size_t)r0 * DIM + col) = v0;
            *(float2*)(Y + (size_t)(r0 + 8) * DIM + col) = v1;
        }
    }
}

// ---------------- scores: for each (b,h): S[m,n] = (q_m . k_n) / 8 ----------
__global__ __launch_bounds__(256)
void scores_kernel(const float* __restrict__ q,
                   const float* __restrict__ k,
                   float* __restrict__ scores)
{
    const int bh = blockIdx.z;
    const int b = bh / NHEAD;
    const int h = bh % NHEAD;
    const int bm = blockIdx.y * 64;
    const int bn = blockIdx.x * 64;

    const float* qb = q + (size_t)b * SEQ * DIM + h * DK;
    const float* kb = k + (size_t)b * SEQ * DIM + h * DK;

    __shared__ float qs[64][DK + 1];
    __shared__ float ks[64][DK + 1];

    const int tid = threadIdx.x;
#pragma unroll
    for (int i = 0; i < 16; i++) {
        int idx = tid + i * 256;
        int r = idx / DK, c = idx % DK;
        qs[r][c] = qb[(size_t)(bm + r) * DIM + c];
        ks[r][c] = kb[(size_t)(bn + r) * DIM + c];
    }
    __syncthreads();

    const int tm = (tid / 16) * 4;
    const int tn = (tid % 16) * 4;

    float acc[4][4];
#pragma unroll
    for (int i = 0; i < 4; i++)
#pragma unroll
        for (int j = 0; j < 4; j++) acc[i][j] = 0.f;

#pragma unroll
    for (int kk = 0; kk < DK; kk++) {
        float a[4], bb[4];
#pragma unroll
        for (int i = 0; i < 4; i++) a[i] = qs[tm + i][kk];
#pragma unroll
        for (int j = 0; j < 4; j++) bb[j] = ks[tn + j][kk];
#pragma unroll
        for (int i = 0; i < 4; i++)
#pragma unroll
            for (int j = 0; j < 4; j++) acc[i][j] += a[i] * bb[j];
    }

    float* sp = scores + (size_t)bh * SEQ * SEQ;
#pragma unroll
    for (int i = 0; i < 4; i++) {
        size_t row = (size_t)(bm + tm + i) * SEQ;
#pragma unroll
        for (int j = 0; j < 4; j++)
            sp[row + bn + tn + j] = acc[i][j] * 0.125f;
    }
}

// ---------------- double softmax over each row of scores --------------------
__global__ __launch_bounds__(256)
void softmax2_kernel(float* __restrict__ scores)
{
    __shared__ float row[SEQ];
    __shared__ float red[256];

    const size_t r = blockIdx.x;
    float* p = scores + r * SEQ;
    const int tid = threadIdx.x;

    for (int i = tid; i < SEQ; i += 256) row[i] = p[i];
    __syncthreads();

#pragma unroll
    for (int pass = 0; pass < 2; pass++) {
        float m = -INFINITY;
        for (int i = tid; i < SEQ; i += 256) m = fmaxf(m, row[i]);
        red[tid] = m; __syncthreads();
        for (int s = 128; s > 0; s >>= 1) {
            if (tid < s) red[tid] = fmaxf(red[tid], red[tid + s]);
            __syncthreads();
        }
        m = red[0]; __syncthreads();
        float sum = 0.f;
        for (int i = tid; i < SEQ; i += 256) {
            float e = __expf(row[i] - m);
            row[i] = e;
            sum += e;
        }
        red[tid] = sum; __syncthreads();
        for (int s = 128; s > 0; s >>= 1) {
            if (tid < s) red[tid] += red[tid + s];
            __syncthreads();
        }
        float inv = 1.0f / red[0]; __syncthreads();
        for (int i = tid; i < SEQ; i += 256) row[i] *= inv;
        __syncthreads();
    }

    for (int i = tid; i < SEQ; i += 256) p[i] = row[i];
}

// ---------------- ctx: for each (b,h): C[m,d] = sum_s attn[m,s] v[s,d] ------
#define CBK 32
__global__ __launch_bounds__(256)
void ctx_kernel(const float* __restrict__ scores,
                const float* __restrict__ v,
                float* __restrict__ ctx)
{
    const int bh = blockIdx.z;
    const int b = bh / NHEAD;
    const int h = bh % NHEAD;
    const int bm = blockIdx.y * 64;

    const float* ap = scores + (size_t)bh * SEQ * SEQ;
    const float* vb = v + (size_t)b * SEQ * DIM + h * DK;

    __shared__ float As[64][CBK + 1];
    __shared__ float Vs[CBK][DK + 1];

    const int tid = threadIdx.x;
    const int tm = (tid / 16) * 4;
    const int tn = (tid % 16) * 4;

    float acc[4][4];
#pragma unroll
    for (int i = 0; i < 4; i++)
#pragma unroll
        for (int j = 0; j < 4; j++) acc[i][j] = 0.f;

    for (int s0 = 0; s0 < SEQ; s0 += CBK) {
#pragma unroll
        for (int i = 0; i < 8; i++) {
            int idx = tid + i * 256;
            int r = idx / CBK, c = idx % CBK;
            As[r][c] = ap[(size_t)(bm + r) * SEQ + s0 + c];
            int vr = idx / DK, vc = idx % DK;
            Vs[vr][vc] = vb[(size_t)(s0 + vr) * DIM + vc];
        }
        __syncthreads();
#pragma unroll
        for (int kk = 0; kk < CBK; kk++) {
            float a[4], bb[4];
#pragma unroll
            for (int i = 0; i < 4; i++) a[i] = As[tm + i][kk];
#pragma unroll
            for (int j = 0; j < 4; j++) bb[j] = Vs[kk][tn + j];
#pragma unroll
            for (int i = 0; i < 4; i++)
#pragma unroll
                for (int j = 0; j < 4; j++) acc[i][j] += a[i] * bb[j];
        }
        __syncthreads();
    }

    float* cp = ctx + (size_t)b * SEQ * DIM + h * DK;
#pragma unroll
    for (int i = 0; i < 4; i++) {
        size_t row = (size_t)(bm + tm + i) * DIM;
#pragma unroll
        for (int j = 0; j < 4; j++)
            cp[row + tn + j] = acc[i][j];
    }
}

// ---------------- residual + layernorm --------------------------------------
__global__ __launch_bounds__(256)
void ln_kernel(const float* __restrict__ proj,
               const float* __restrict__ Qres,
               const float* __restrict__ g,
               const float* __restrict__ bta,
               float* __restrict__ out)
{
    __shared__ float red[256];
    const size_t row = blockIdx.x;
    const float* x1 = proj + row * DIM;
    const float* x2 = Qres + row * DIM;
    const int tid = threadIdx.x;

    float vals[4];
    float sum = 0.f;
#pragma unroll
    for (int j = 0; j < 4; j++) {
        int i = tid + j * 256;
        vals[j] = x1[i] + x2[i];
        sum += vals[j];
    }
    red[tid] = sum; __syncthreads();
    for (int s = 128; s > 0; s >>= 1) {
        if (tid < s) red[tid] += red[tid + s];
        __syncthreads();
    }
    float mu = red[0] / DIM; __syncthreads();

    float sq = 0.f;
#pragma unroll
    for (int j = 0; j < 4; j++) {
        float d = vals[j] - mu;
        sq += d * d;
    }
    red[tid] = sq; __syncthreads();
    for (int s = 128; s > 0; s >>= 1) {
        if (tid < s) red[tid] += red[tid + s];
        __syncthreads();
    }
    float rstd = rsqrtf(red[0] / DIM + LN_EPS);

    float* op = out + row * DIM;
#pragma unroll
    for (int j = 0; j < 4; j++) {
        int i = tid + j * 256;
        op[i] = (vals[j] - mu) * rstd * g[i] + bta[i];
    }
}

// ---------------- launch -----------------------------------------------------
extern "C" void kernel_launch(void* const* d_in, const int* in_sizes, int n_in,
                              void* d_out, int out_size)
{
    const float* Q   = (const float*)d_in[0];
    const float* K   = (const float*)d_in[1];
    const float* V   = (const float*)d_in[2];
    const float* Wq  = (const float*)d_in[3];
    const float* bq  = (const float*)d_in[4];
    const float* Wk  = (const float*)d_in[5];
    const float* bk  = (const float*)d_in[6];
    const float* Wv  = (const float*)d_in[7];
    const float* bv  = (const float*)d_in[8];
    const float* Wo  = (const float*)d_in[9];
    const float* bo  = (const float*)d_in[10];
    const float* lng = (const float*)d_in[11];
    const float* lnb = (const float*)d_in[12];
    float* out = (float*)d_out;

    float *q, *k, *v, *ctx, *outb, *scores;
    __nv_bfloat16 *a_hi, *a_lo, *w_hi, *w_lo;
    cudaGetSymbolAddress((void**)&q,      g_q);
    cudaGetSymbolAddress((void**)&k,      g_k);
    cudaGetSymbolAddress((void**)&v,      g_v);
    cudaGetSymbolAddress((void**)&ctx,    g_ctx);
    cudaGetSymbolAddress((void**)&outb,   g_outb);
    cudaGetSymbolAddress((void**)&scores, g_scores);
    cudaGetSymbolAddress((void**)&a_hi,   g_a_hi);
    cudaGetSymbolAddress((void**)&a_lo,   g_a_lo);
    cudaGetSymbolAddress((void**)&w_hi,   g_w_hi);
    cudaGetSymbolAddress((void**)&w_lo,   g_w_lo);

    cudaFuncSetAttribute(tc_gemm_kernel,
                         cudaFuncAttributeMaxDynamicSharedMemorySize,
                         TCG_SMEM);

    const int n4_in = MROWS * DIM / 4;
    const int n4_w  = DIM * DIM / 4;
    dim3 ggemm(DIM / 128, MROWS / 128);  // (8, 32)

    // Q projection
    cvt_hilo_kernel<<<n4_in / 256, 256>>>(Q, a_hi, a_lo, n4_in);
    cvt_hilo_kernel<<<n4_w / 256, 256>>>(Wq, w_hi, w_lo, n4_w);
    tc_gemm_kernel<<<ggemm, 256, TCG_SMEM>>>(a_hi, a_lo, w_hi, w_lo, bq, q);
    // K projection
    cvt_hilo_kernel<<<n4_in / 256, 256>>>(K, a_hi, a_lo, n4_in);
    cvt_hilo_kernel<<<n4_w / 256, 256>>>(Wk, w_hi, w_lo, n4_w);
    tc_gemm_kernel<<<ggemm, 256, TCG_SMEM>>>(a_hi, a_lo, w_hi, w_lo, bk, k);
    // V projection
    cvt_hilo_kernel<<<n4_in / 256, 256>>>(V, a_hi, a_lo, n4_in);
    cvt_hilo_kernel<<<n4_w / 256, 256>>>(Wv, w_hi, w_lo, n4_w);
    tc_gemm_kernel<<<ggemm, 256, TCG_SMEM>>>(a_hi, a_lo, w_hi, w_lo, bv, v);

    // attention (fp32 SIMT this round)
    dim3 gsc(SEQ / 64, SEQ / 64, BATCH * NHEAD);
    scores_kernel<<<gsc, 256>>>(q, k, scores);
    softmax2_kernel<<<BATCH * NHEAD * SEQ, 256>>>(scores);
    dim3 gctx(1, SEQ / 64, BATCH * NHEAD);
    ctx_kernel<<<gctx, 256>>>(scores, v, ctx);

    // output projection
    cvt_hilo_kernel<<<n4_in / 256, 256>>>(ctx, a_hi, a_lo, n4_in);
    cvt_hilo_kernel<<<n4_w / 256, 256>>>(Wo, w_hi, w_lo, n4_w);
    tc_gemm_kernel<<<ggemm, 256, TCG_SMEM>>>(a_hi, a_lo, w_hi, w_lo, bo, outb);

    ln_kernel<<<MROWS, 256>>>(outb, Q, lng, lnb, out);
}

// round 4
// speedup vs baseline: 3.5776x; 2.0095x over previous
#include <cuda_runtime.h>
#include <cuda_bf16.h>
#include <cstdint>
#include <math.h>

// Problem constants
#define BATCH 4
#define SEQ   1024
#define DIM   1024
#define NHEAD 16
#define DK    64
#define MROWS (BATCH * SEQ)   // 4096
#define LN_EPS 1e-5f

typedef __nv_bfloat16 bf16;
typedef __nv_bfloat162 bf162;

// ---------------- scratch (device globals: no allocs allowed) ----------------
__device__ bf16 g_inb[(size_t)MROWS * DIM];                 // input bf16
__device__ bf16 g_qb[(size_t)MROWS * DIM];
__device__ bf16 g_kb[(size_t)MROWS * DIM];
__device__ bf16 g_vb[(size_t)MROWS * DIM];
__device__ bf16 g_sc[(size_t)BATCH * NHEAD * SEQ * SEQ];    // 128 MB bf16 scores/attn
__device__ bf16 g_a_hi[(size_t)MROWS * DIM];                // ctx hi
__device__ bf16 g_a_lo[(size_t)MROWS * DIM];                // ctx lo
__device__ bf16 g_w_hi[(size_t)DIM * DIM];
__device__ bf16 g_w_lo[(size_t)DIM * DIM];
__device__ float g_outb[(size_t)MROWS * DIM];

// =================== baseline-PTX helpers ====================================
__device__ __forceinline__ uint32_t s2u(const void* p) {
    uint32_t a;
    asm("{ .reg .u64 t; cvta.to.shared.u64 t, %1; cvt.u32.u64 %0, t; }"
        : "=r"(a) : "l"(p));
    return a;
}
__device__ __forceinline__ void cp16(uint32_t dst, const void* src) {
    asm volatile("cp.async.cg.shared.global [%0], [%1], 16;"
                 :: "r"(dst), "l"(src) : "memory");
}
__device__ __forceinline__ void cp_commit() {
    asm volatile("cp.async.commit_group;" ::: "memory");
}
template <int N>
__device__ __forceinline__ void cp_wait() {
    asm volatile("cp.async.wait_group %0;" :: "n"(N) : "memory");
}
__device__ __forceinline__ void ldsm4(uint32_t& r0, uint32_t& r1,
                                      uint32_t& r2, uint32_t& r3, uint32_t a) {
    asm volatile("ldmatrix.sync.aligned.m8n8.x4.shared.b16 {%0,%1,%2,%3}, [%4];"
                 : "=r"(r0), "=r"(r1), "=r"(r2), "=r"(r3) : "r"(a));
}
__device__ __forceinline__ void ldsm4t(uint32_t& r0, uint32_t& r1,
                                       uint32_t& r2, uint32_t& r3, uint32_t a) {
    asm volatile("ldmatrix.sync.aligned.m8n8.x4.trans.shared.b16 {%0,%1,%2,%3}, [%4];"
                 : "=r"(r0), "=r"(r1), "=r"(r2), "=r"(r3) : "r"(a));
}
__device__ __forceinline__ void mma16816(float* c, const uint32_t* a,
                                         const uint32_t* b) {
    asm volatile("mma.sync.aligned.m16n8k16.row.col.f32.bf16.bf16.f32 "
                 "{%0,%1,%2,%3}, {%4,%5,%6,%7}, {%8,%9}, {%0,%1,%2,%3};"
                 : "+f"(c[0]), "+f"(c[1]), "+f"(c[2]), "+f"(c[3])
                 : "r"(a[0]), "r"(a[1]), "r"(a[2]), "r"(a[3]),
                   "r"(b[0]), "r"(b[1]));
}
// swizzled byte offset within a tile of 128B rows (8 chunks of 16B)
__device__ __forceinline__ uint32_t tile_off(int row, int chunk) {
    return (uint32_t)(row * 128 + ((chunk ^ (row & 7)) << 4));
}

// =================== conversions =============================================
__global__ __launch_bounds__(256)
void cvt_bf_kernel(const float* __restrict__ x, bf16* __restrict__ y, int n4)
{
    int i = blockIdx.x * blockDim.x + threadIdx.x;
    if (i >= n4) return;
    float4 v = ((const float4*)x)[i];
    ((bf162*)y)[2 * i]     = bf162(__float2bfloat16(v.x), __float2bfloat16(v.y));
    ((bf162*)y)[2 * i + 1] = bf162(__float2bfloat16(v.z), __float2bfloat16(v.w));
}

__global__ __launch_bounds__(256)
void cvt_hilo_kernel(const float* __restrict__ x,
                     bf16* __restrict__ hi, bf16* __restrict__ lo, int n4)
{
    int i = blockIdx.x * blockDim.x + threadIdx.x;
    if (i >= n4) return;
    float4 v = ((const float4*)x)[i];
    bf16 h0 = __float2bfloat16(v.x);
    bf16 h1 = __float2bfloat16(v.y);
    bf16 h2 = __float2bfloat16(v.z);
    bf16 h3 = __float2bfloat16(v.w);
    bf16 l0 = __float2bfloat16(v.x - __bfloat162float(h0));
    bf16 l1 = __float2bfloat16(v.y - __bfloat162float(h1));
    bf16 l2 = __float2bfloat16(v.z - __bfloat162float(h2));
    bf16 l3 = __float2bfloat16(v.w - __bfloat162float(h3));
    ((bf162*)hi)[2 * i]     = bf162(h0, h1);
    ((bf162*)hi)[2 * i + 1] = bf162(h2, h3);
    ((bf162*)lo)[2 * i]     = bf162(l0, l1);
    ((bf162*)lo)[2 * i + 1] = bf162(l2, l3);
}

// =================== single-bf16 GEMM: Yb[M,N] = bf16(A@W^T + bias) ==========
// CTA 128x128, BK=64, 2-stage cp.async. 8 warps 4x2, warp tile 32x64.
#define BFG_STAGE 32768
#define BFG_SMEM  (2 * BFG_STAGE)

__global__ __launch_bounds__(256)
void gemm_bf_kernel(const bf16* __restrict__ A, const bf16* __restrict__ W,
                    const float* __restrict__ bias, bf16* __restrict__ Yb)
{
    extern __shared__ char tsm[];
    const int tid = threadIdx.x;
    const int wid = tid >> 5;
    const int lane = tid & 31;
    const int wm = wid >> 1;
    const int wn = wid & 1;
    const int bm = blockIdx.y * 128;
    const int bn = blockIdx.x * 128;
    const uint32_t sbase = s2u(tsm);

    float acc[2][8][4];
#pragma unroll
    for (int i = 0; i < 2; i++)
#pragma unroll
        for (int j = 0; j < 8; j++)
#pragma unroll
            for (int r = 0; r < 4; r++) acc[i][j][r] = 0.f;

    auto load_stage = [&](int kt, int s) {
        const uint32_t stage = sbase + s * BFG_STAGE;
#pragma unroll
        for (int i = 0; i < 8; i++) {
            int u = tid + i * 256;
            int sub = u >> 10;
            int idx = u & 1023;
            int row = idx >> 3;
            int c = idx & 7;
            const bf16* src = sub ? W + (size_t)(bn + row) * DIM
                                  : A + (size_t)(bm + row) * DIM;
            cp16(stage + sub * 16384 + tile_off(row, c), src + kt * 64 + c * 8);
        }
        cp_commit();
    };

    load_stage(0, 0);
    for (int kt = 0; kt < 16; kt++) {
        if (kt < 15) { load_stage(kt + 1, (kt + 1) & 1); cp_wait<1>(); }
        else cp_wait<0>();
        __syncthreads();
        const uint32_t st = sbase + (kt & 1) * BFG_STAGE;
#pragma unroll
        for (int ks = 0; ks < 4; ks++) {
            uint32_t af[2][4];
#pragma unroll
            for (int mt = 0; mt < 2; mt++) {
                int row = wm * 32 + mt * 16 + (lane & 15);
                int chunk = ks * 2 + (lane >> 4);
                ldsm4(af[mt][0], af[mt][1], af[mt][2], af[mt][3],
                      st + tile_off(row, chunk));
            }
            uint32_t bfg[4][4];
#pragma unroll
            for (int p = 0; p < 4; p++) {
                int n = wn * 64 + p * 16 + ((lane >> 4) << 3) + (lane & 7);
                int chunk = ks * 2 + ((lane >> 3) & 1);
                ldsm4(bfg[p][0], bfg[p][1], bfg[p][2], bfg[p][3],
                      st + 16384 + tile_off(n, chunk));
            }
#pragma unroll
            for (int mt = 0; mt < 2; mt++)
#pragma unroll
                for (int nt = 0; nt < 8; nt++)
                    mma16816(acc[mt][nt], af[mt], &bfg[nt >> 1][(nt & 1) * 2]);
        }
        __syncthreads();
    }

    const int gq = lane >> 2;
    const int tq = lane & 3;
#pragma unroll
    for (int mt = 0; mt < 2; mt++)
#pragma unroll
        for (int nt = 0; nt < 8; nt++) {
            int col = bn + wn * 64 + nt * 8 + tq * 2;
            float bx = bias[col], by = bias[col + 1];
            int r0 = bm + wm * 32 + mt * 16 + gq;
            *(bf162*)(Yb + (size_t)r0 * DIM + col) =
                bf162(__float2bfloat16(acc[mt][nt][0] + bx),
                      __float2bfloat16(acc[mt][nt][1] + by));
            *(bf162*)(Yb + (size_t)(r0 + 8) * DIM + col) =
                bf162(__float2bfloat16(acc[mt][nt][2] + bx),
                      __float2bfloat16(acc[mt][nt][3] + by));
        }
}

// =================== split GEMM (O-projection): Y = A@W^T + bias (fp32) =====
#define TCG_STAGE 65536
#define TCG_SMEM  (2 * TCG_STAGE)

__global__ __launch_bounds__(256)
void tc_gemm_kernel(const bf16* __restrict__ Ahi, const bf16* __restrict__ Alo,
                    const bf16* __restrict__ Bhi, const bf16* __restrict__ Blo,
                    const float* __restrict__ bias, float* __restrict__ Y)
{
    extern __shared__ char tsm[];
    const int tid = threadIdx.x;
    const int wid = tid >> 5;
    const int lane = tid & 31;
    const int wm = wid >> 1;
    const int wn = wid & 1;
    const int bm = blockIdx.y * 128;
    const int bn = blockIdx.x * 128;
    const uint32_t sbase = s2u(tsm);

    float acc[2][8][4];
#pragma unroll
    for (int i = 0; i < 2; i++)
#pragma unroll
        for (int j = 0; j < 8; j++)
#pragma unroll
            for (int r = 0; r < 4; r++) acc[i][j][r] = 0.f;

    auto load_stage = [&](int kt, int s) {
        const uint32_t stage = sbase + s * TCG_STAGE;
#pragma unroll
        for (int i = 0; i < 16; i++) {
            int u = tid + i * 256;
            int sub = u >> 10;
            int idx = u & 1023;
            int row = idx >> 3;
            int c = idx & 7;
            const bf16* src =
                (sub == 0) ? Ahi + (size_t)(bm + row) * DIM
              : (sub == 1) ? Alo + (size_t)(bm + row) * DIM
              : (sub == 2) ? Bhi + (size_t)(bn + row) * DIM
                           : Blo + (size_t)(bn + row) * DIM;
            cp16(stage + sub * 16384 + tile_off(row, c), src + kt * 64 + c * 8);
        }
        cp_commit();
    };

    load_stage(0, 0);
    for (int kt = 0; kt < 16; kt++) {
        if (kt < 15) { load_stage(kt + 1, (kt + 1) & 1); cp_wait<1>(); }
        else cp_wait<0>();
        __syncthreads();
        const uint32_t st = sbase + (kt & 1) * TCG_STAGE;
#pragma unroll
        for (int ks = 0; ks < 4; ks++) {
            uint32_t ahi[2][4], alo[2][4];
#pragma unroll
            for (int mt = 0; mt < 2; mt++) {
                int row = wm * 32 + mt * 16 + (lane & 15);
                int chunk = ks * 2 + (lane >> 4);
                uint32_t a0 = st + tile_off(row, chunk);
                ldsm4(ahi[mt][0], ahi[mt][1], ahi[mt][2], ahi[mt][3], a0);
                ldsm4(alo[mt][0], alo[mt][1], alo[mt][2], alo[mt][3], a0 + 16384);
            }
            uint32_t bh[4][4], bl[4][4];
#pragma unroll
            for (int p = 0; p < 4; p++) {
                int n = wn * 64 + p * 16 + ((lane >> 4) << 3) + (lane & 7);
                int chunk = ks * 2 + ((lane >> 3) & 1);
                uint32_t a0 = st + 32768 + tile_off(n, chunk);
                ldsm4(bh[p][0], bh[p][1], bh[p][2], bh[p][3], a0);
                ldsm4(bl[p][0], bl[p][1], bl[p][2], bl[p][3], a0 + 16384);
            }
#pragma unroll
            for (int mt = 0; mt < 2; mt++)
#pragma unroll
                for (int nt = 0; nt < 8; nt++) {
                    const uint32_t* bhp = &bh[nt >> 1][(nt & 1) * 2];
                    const uint32_t* blp = &bl[nt >> 1][(nt & 1) * 2];
                    mma16816(acc[mt][nt], ahi[mt], bhp);
                    mma16816(acc[mt][nt], ahi[mt], blp);
                    mma16816(acc[mt][nt], alo[mt], bhp);
                }
        }
        __syncthreads();
    }

    const int gq = lane >> 2;
    const int tq = lane & 3;
#pragma unroll
    for (int mt = 0; mt < 2; mt++)
#pragma unroll
        for (int nt = 0; nt < 8; nt++) {
            int col = bn + wn * 64 + nt * 8 + tq * 2;
            float bx = bias[col], by = bias[col + 1];
            int r0 = bm + wm * 32 + mt * 16 + gq;
            *(float2*)(Y + (size_t)r0 * DIM + col) =
                make_float2(acc[mt][nt][0] + bx, acc[mt][nt][1] + by);
            *(float2*)(Y + (size_t)(r0 + 8) * DIM + col) =
                make_float2(acc[mt][nt][2] + bx, acc[mt][nt][3] + by);
        }
}

// =================== scores: S = bf16(q . k^T / 8) per (b,h) =================
// CTA = (128 q-rows x 128 keys) for one bh. K-dim = 64 (single tile).
__global__ __launch_bounds__(256)
void scores_mma_kernel(const bf16* __restrict__ qb, const bf16* __restrict__ kb,
                       bf16* __restrict__ sc)
{
    __shared__ char ssm[32768];
    const int tid = threadIdx.x;
    const int wid = tid >> 5;
    const int lane = tid & 31;
    const int wm = wid >> 1;
    const int wn = wid & 1;
    const int bh = blockIdx.z;
    const int b = bh >> 4;
    const int h = bh & 15;
    const int bm = blockIdx.y * 128;
    const int bn = blockIdx.x * 128;
    const uint32_t sbase = s2u(ssm);

    // load q tile (128x64) and k tile (128x64)
#pragma unroll
    for (int i = 0; i < 8; i++) {
        int u = tid + i * 256;
        int sub = u >> 10;
        int idx = u & 1023;
        int row = idx >> 3;
        int c = idx & 7;
        const bf16* src = sub
            ? kb + (size_t)(b * SEQ + bn + row) * DIM + h * DK
            : qb + (size_t)(b * SEQ + bm + row) * DIM + h * DK;
        cp16(sbase + sub * 16384 + tile_off(row, c), src + c * 8);
    }
    cp_commit();
    cp_wait<0>();
    __syncthreads();

    float acc[2][8][4];
#pragma unroll
    for (int i = 0; i < 2; i++)
#pragma unroll
        for (int j = 0; j < 8; j++)
#pragma unroll
            for (int r = 0; r < 4; r++) acc[i][j][r] = 0.f;

#pragma unroll
    for (int ks = 0; ks < 4; ks++) {
        uint32_t af[2][4];
#pragma unroll
        for (int mt = 0; mt < 2; mt++) {
            int row = wm * 32 + mt * 16 + (lane & 15);
            int chunk = ks * 2 + (lane >> 4);
            ldsm4(af[mt][0], af[mt][1], af[mt][2], af[mt][3],
                  sbase + tile_off(row, chunk));
        }
        uint32_t bfg[4][4];
#pragma unroll
        for (int p = 0; p < 4; p++) {
            int n = wn * 64 + p * 16 + ((lane >> 4) << 3) + (lane & 7);
            int chunk = ks * 2 + ((lane >> 3) & 1);
            ldsm4(bfg[p][0], bfg[p][1], bfg[p][2], bfg[p][3],
                  sbase + 16384 + tile_off(n, chunk));
        }
#pragma unroll
        for (int mt = 0; mt < 2; mt++)
#pragma unroll
            for (int nt = 0; nt < 8; nt++)
                mma16816(acc[mt][nt], af[mt], &bfg[nt >> 1][(nt & 1) * 2]);
    }

    bf16* sp = sc + (size_t)bh * SEQ * SEQ;
    const int gq = lane >> 2;
    const int tq = lane & 3;
#pragma unroll
    for (int mt = 0; mt < 2; mt++)
#pragma unroll
        for (int nt = 0; nt < 8; nt++) {
            int col = bn + wn * 64 + nt * 8 + tq * 2;
            int r0 = bm + wm * 32 + mt * 16 + gq;
            *(bf162*)(sp + (size_t)r0 * SEQ + col) =
                bf162(__float2bfloat16(acc[mt][nt][0] * 0.125f),
                      __float2bfloat16(acc[mt][nt][1] * 0.125f));
            *(bf162*)(sp + (size_t)(r0 + 8) * SEQ + col) =
                bf162(__float2bfloat16(acc[mt][nt][2] * 0.125f),
                      __float2bfloat16(acc[mt][nt][3] * 0.125f));
        }
}

// =================== double softmax (bf16 in-place, fp32 math) ===============
__global__ __launch_bounds__(256)
void softmax2_bf_kernel(bf16* __restrict__ sc)
{
    __shared__ float row[SEQ];
    __shared__ float red[256];
    bf16* p = sc + (size_t)blockIdx.x * SEQ;
    const int tid = threadIdx.x;

    // load 4 values per thread
#pragma unroll
    for (int j = 0; j < 2; j++) {
        bf162 v = ((const bf162*)p)[tid + j * 256];
        row[2 * (tid + j * 256)] = __bfloat162float(v.x);
        row[2 * (tid + j * 256) + 1] = __bfloat162float(v.y);
    }
    __syncthreads();

#pragma unroll
    for (int pass = 0; pass < 2; pass++) {
        float m = -INFINITY;
        for (int i = tid; i < SEQ; i += 256) m = fmaxf(m, row[i]);
        red[tid] = m; __syncthreads();
        for (int s = 128; s > 0; s >>= 1) {
            if (tid < s) red[tid] = fmaxf(red[tid], red[tid + s]);
            __syncthreads();
        }
        m = red[0]; __syncthreads();
        float sum = 0.f;
        for (int i = tid; i < SEQ; i += 256) {
            float e = __expf(row[i] - m);
            row[i] = e;
            sum += e;
        }
        red[tid] = sum; __syncthreads();
        for (int s = 128; s > 0; s >>= 1) {
            if (tid < s) red[tid] += red[tid + s];
            __syncthreads();
        }
        float inv = 1.0f / red[0]; __syncthreads();
        for (int i = tid; i < SEQ; i += 256) row[i] *= inv;
        __syncthreads();
    }

#pragma unroll
    for (int j = 0; j < 2; j++) {
        int i = tid + j * 256;
        ((bf162*)p)[i] = bf162(__float2bfloat16(row[2 * i]),
                               __float2bfloat16(row[2 * i + 1]));
    }
}

// =================== ctx: C = attn . V per (b,h), hi/lo bf16 out =============
// CTA = 128 q-rows x 64 dims; contraction over 1024 keys in 16 chunks of 64.
// 8 warps, each 16 rows x 64 dims.
#define CTX_STAGE 24576   // attn 16KB + v 8KB
#define CTX_SMEM  (2 * CTX_STAGE)

__global__ __launch_bounds__(256)
void ctx_mma_kernel(const bf16* __restrict__ sc, const bf16* __restrict__ vb,
                    bf16* __restrict__ chi, bf16* __restrict__ clo)
{
    extern __shared__ char csm[];
    const int tid = threadIdx.x;
    const int wid = tid >> 5;
    const int lane = tid & 31;
    const int bh = blockIdx.y;
    const int b = bh >> 4;
    const int h = bh & 15;
    const int bm = blockIdx.x * 128;
    const uint32_t sbase = s2u(csm);

    const bf16* sp = sc + (size_t)bh * SEQ * SEQ;
    const bf16* vp = vb + (size_t)b * SEQ * DIM + h * DK;

    float acc[8][4];
#pragma unroll
    for (int j = 0; j < 8; j++)
#pragma unroll
        for (int r = 0; r < 4; r++) acc[j][r] = 0.f;

    auto load_stage = [&](int kt, int s) {
        const uint32_t stage = sbase + s * CTX_STAGE;
        // attn: 128 rows x 8 chunks
#pragma unroll
        for (int i = 0; i < 4; i++) {
            int u = tid + i * 256;
            int row = u >> 3;
            int c = u & 7;
            cp16(stage + tile_off(row, c),
                 sp + (size_t)(bm + row) * SEQ + kt * 64 + c * 8);
        }
        // v: 64 rows x 8 chunks
#pragma unroll
        for (int i = 0; i < 2; i++) {
            int u = tid + i * 256;
            int row = u >> 3;
            int c = u & 7;
            cp16(stage + 16384 + tile_off(row, c),
                 vp + (size_t)(kt * 64 + row) * DIM + c * 8);
        }
        cp_commit();
    };

    load_stage(0, 0);
    for (int kt = 0; kt < 16; kt++) {
        if (kt < 15) { load_stage(kt + 1, (kt + 1) & 1); cp_wait<1>(); }
        else cp_wait<0>();
        __syncthreads();
        const uint32_t st = sbase + (kt & 1) * CTX_STAGE;
#pragma unroll
        for (int ks = 0; ks < 4; ks++) {
            uint32_t af[4];
            {
                int row = wid * 16 + (lane & 15);
                int chunk = ks * 2 + (lane >> 4);
                ldsm4(af[0], af[1], af[2], af[3], st + tile_off(row, chunk));
            }
            uint32_t bfg[4][4];
#pragma unroll
            for (int p = 0; p < 4; p++) {
                // trans load of v: matrices (k8 x n8): m0=k0-7/d0-7 m1=k8-15/d0-7
                // m2=k0-7/d8-15 m3=k8-15/d8-15
                int mat = lane >> 3;
                int l = lane & 7;
                int srow = ks * 16 + ((mat & 1) << 3) + l;
                int dchunk = p * 2 + (mat >> 1);
                ldsm4t(bfg[p][0], bfg[p][1], bfg[p][2], bfg[p][3],
                       st + 16384 + tile_off(srow, dchunk));
            }
#pragma unroll
            for (int nt = 0; nt < 8; nt++)
                mma16816(acc[nt], af, &bfg[nt >> 1][(nt & 1) * 2]);
        }
        __syncthreads();
    }

    const int gq = lane >> 2;
    const int tq = lane & 3;
#pragma unroll
    for (int nt = 0; nt < 8; nt++) {
        int col = nt * 8 + tq * 2;
#pragma unroll
        for (int half = 0; half < 2; half++) {
            int r = bm + wid * 16 + half * 8 + gq;
            float x = acc[nt][half * 2], y = acc[nt][half * 2 + 1];
            bf16 hx = __float2bfloat16(x);
            bf16 hy = __float2bfloat16(y);
            bf16 lx = __float2bfloat16(x - __bfloat162float(hx));
            bf16 ly = __float2bfloat16(y - __bfloat162float(hy));
            size_t off = (size_t)(b * SEQ + r) * DIM + h * DK + col;
            *(bf162*)(chi + off) = bf162(hx, hy);
            *(bf162*)(clo + off) = bf162(lx, ly);
        }
    }
}

// ---------------- residual + layernorm --------------------------------------
__global__ __launch_bounds__(256)
void ln_kernel(const float* __restrict__ proj, const float* __restrict__ Qres,
               const float* __restrict__ g, const float* __restrict__ bta,
               float* __restrict__ out)
{
    __shared__ float red[256];
    const size_t row = blockIdx.x;
    const float* x1 = proj + row * DIM;
    const float* x2 = Qres + row * DIM;
    const int tid = threadIdx.x;

    float vals[4];
    float sum = 0.f;
#pragma unroll
    for (int j = 0; j < 4; j++) {
        int i = tid + j * 256;
        vals[j] = x1[i] + x2[i];
        sum += vals[j];
    }
    red[tid] = sum; __syncthreads();
    for (int s = 128; s > 0; s >>= 1) {
        if (tid < s) red[tid] += red[tid + s];
        __syncthreads();
    }
    float mu = red[0] / DIM; __syncthreads();

    float sq = 0.f;
#pragma unroll
    for (int j = 0; j < 4; j++) {
        float d = vals[j] - mu;
        sq += d * d;
    }
    red[tid] = sq; __syncthreads();
    for (int s = 128; s > 0; s >>= 1) {
        if (tid < s) red[tid] += red[tid + s];
        __syncthreads();
    }
    float rstd = rsqrtf(red[0] / DIM + LN_EPS);

    float* op = out + row * DIM;
#pragma unroll
    for (int j = 0; j < 4; j++) {
        int i = tid + j * 256;
        op[i] = (vals[j] - mu) * rstd * g[i] + bta[i];
    }
}

// ---------------- launch -----------------------------------------------------
extern "C" void kernel_launch(void* const* d_in, const int* in_sizes, int n_in,
                              void* d_out, int out_size)
{
    const float* Q   = (const float*)d_in[0];
    const float* K   = (const float*)d_in[1];
    const float* V   = (const float*)d_in[2];
    const float* Wq  = (const float*)d_in[3];
    const float* bq  = (const float*)d_in[4];
    const float* Wk  = (const float*)d_in[5];
    const float* bk  = (const float*)d_in[6];
    const float* Wv  = (const float*)d_in[7];
    const float* bv  = (const float*)d_in[8];
    const float* Wo  = (const float*)d_in[9];
    const float* bo  = (const float*)d_in[10];
    const float* lng = (const float*)d_in[11];
    const float* lnb = (const float*)d_in[12];
    float* out = (float*)d_out;

    bf16 *inb, *qb, *kb, *vb, *scb, *a_hi, *a_lo, *w_hi, *w_lo;
    float* outb;
    cudaGetSymbolAddress((void**)&inb,  g_inb);
    cudaGetSymbolAddress((void**)&qb,   g_qb);
    cudaGetSymbolAddress((void**)&kb,   g_kb);
    cudaGetSymbolAddress((void**)&vb,   g_vb);
    cudaGetSymbolAddress((void**)&scb,  g_sc);
    cudaGetSymbolAddress((void**)&a_hi, g_a_hi);
    cudaGetSymbolAddress((void**)&a_lo, g_a_lo);
    cudaGetSymbolAddress((void**)&w_hi, g_w_hi);
    cudaGetSymbolAddress((void**)&w_lo, g_w_lo);
    cudaGetSymbolAddress((void**)&outb, g_outb);

    cudaFuncSetAttribute(gemm_bf_kernel,
                         cudaFuncAttributeMaxDynamicSharedMemorySize, BFG_SMEM);
    cudaFuncSetAttribute(tc_gemm_kernel,
                         cudaFuncAttributeMaxDynamicSharedMemorySize, TCG_SMEM);
    cudaFuncSetAttribute(ctx_mma_kernel,
                         cudaFuncAttributeMaxDynamicSharedMemorySize, CTX_SMEM);

    const int n4_in = MROWS * DIM / 4;
    const int n4_w  = DIM * DIM / 4;
    dim3 ggemm(DIM / 128, MROWS / 128);   // (8, 32)

    // Q/K/V projections (single bf16)
    cvt_bf_kernel<<<n4_in / 256, 256>>>(Q, inb, n4_in);
    cvt_bf_kernel<<<n4_w / 256, 256>>>(Wq, w_hi, n4_w);
    gemm_bf_kernel<<<ggemm, 256, BFG_SMEM>>>(inb, w_hi, bq, qb);

    cvt_bf_kernel<<<n4_in / 256, 256>>>(K, inb, n4_in);
    cvt_bf_kernel<<<n4_w / 256, 256>>>(Wk, w_hi, n4_w);
    gemm_bf_kernel<<<ggemm, 256, BFG_SMEM>>>(inb, w_hi, bk, kb);

    cvt_bf_kernel<<<n4_in / 256, 256>>>(V, inb, n4_in);
    cvt_bf_kernel<<<n4_w / 256, 256>>>(Wv, w_hi, n4_w);
    gemm_bf_kernel<<<ggemm, 256, BFG_SMEM>>>(inb, w_hi, bv, vb);

    // attention (tensor cores)
    dim3 gsc(SEQ / 128, SEQ / 128, BATCH * NHEAD);   // (8,8,64)
    scores_mma_kernel<<<gsc, 256>>>(qb, kb, scb);

    softmax2_bf_kernel<<<BATCH * NHEAD * SEQ, 256>>>(scb);

    dim3 gctx(SEQ / 128, BATCH * NHEAD);             // (8,64)
    ctx_mma_kernel<<<gctx, 256, CTX_SMEM>>>(scb, vb, a_hi, a_lo);

    // O-projection (split bf16x3 for accuracy)
    cvt_hilo_kernel<<<n4_w / 256, 256>>>(Wo, w_hi, w_lo, n4_w);
    tc_gemm_kernel<<<ggemm, 256, TCG_SMEM>>>(a_hi, a_lo, w_hi, w_lo, bo, outb);

    ln_kernel<<<MROWS, 256>>>(outb, Q, lng, lnb, out);
}

// round 5
// speedup vs baseline: 7.0133x; 1.9603x over previous
#include <cuda_runtime.h>
#include <cuda_bf16.h>
#include <cstdint>
#include <math.h>

// Problem constants
#define BATCH 4
#define SEQ   1024
#define DIM   1024
#define NHEAD 16
#define DK    64
#define MROWS (BATCH * SEQ)   // 4096
#define LN_EPS 1e-5f

typedef __nv_bfloat16 bf16;
typedef __nv_bfloat162 bf162;

// ---------------- scratch (device globals: no allocs allowed) ----------------
__device__ bf16 g_inb[(size_t)MROWS * DIM];   // bf16 input staging
__device__ bf16 g_qb[(size_t)MROWS * DIM];
__device__ bf16 g_kb[(size_t)MROWS * DIM];
__device__ bf16 g_vb[(size_t)MROWS * DIM];
__device__ bf16 g_ctxb[(size_t)MROWS * DIM];  // ctx bf16
__device__ bf16 g_wb[(size_t)DIM * DIM];      // bf16 weight staging
__device__ float g_outb[(size_t)MROWS * DIM];

// =================== baseline-PTX helpers ====================================
__device__ __forceinline__ uint32_t s2u(const void* p) {
    uint32_t a;
    asm("{ .reg .u64 t; cvta.to.shared.u64 t, %1; cvt.u32.u64 %0, t; }"
        : "=r"(a) : "l"(p));
    return a;
}
__device__ __forceinline__ void cp16(uint32_t dst, const void* src) {
    asm volatile("cp.async.cg.shared.global [%0], [%1], 16;"
                 :: "r"(dst), "l"(src) : "memory");
}
__device__ __forceinline__ void cp_commit() {
    asm volatile("cp.async.commit_group;" ::: "memory");
}
template <int N>
__device__ __forceinline__ void cp_wait() {
    asm volatile("cp.async.wait_group %0;" :: "n"(N) : "memory");
}
__device__ __forceinline__ void ldsm4(uint32_t& r0, uint32_t& r1,
                                      uint32_t& r2, uint32_t& r3, uint32_t a) {
    asm volatile("ldmatrix.sync.aligned.m8n8.x4.shared.b16 {%0,%1,%2,%3}, [%4];"
                 : "=r"(r0), "=r"(r1), "=r"(r2), "=r"(r3) : "r"(a));
}
__device__ __forceinline__ void ldsm4t(uint32_t& r0, uint32_t& r1,
                                       uint32_t& r2, uint32_t& r3, uint32_t a) {
    asm volatile("ldmatrix.sync.aligned.m8n8.x4.trans.shared.b16 {%0,%1,%2,%3}, [%4];"
                 : "=r"(r0), "=r"(r1), "=r"(r2), "=r"(r3) : "r"(a));
}
__device__ __forceinline__ void mma16816(float* c, const uint32_t* a,
                                         const uint32_t* b) {
    asm volatile("mma.sync.aligned.m16n8k16.row.col.f32.bf16.bf16.f32 "
                 "{%0,%1,%2,%3}, {%4,%5,%6,%7}, {%8,%9}, {%0,%1,%2,%3};"
                 : "+f"(c[0]), "+f"(c[1]), "+f"(c[2]), "+f"(c[3])
                 : "r"(a[0]), "r"(a[1]), "r"(a[2]), "r"(a[3]),
                   "r"(b[0]), "r"(b[1]));
}
// swizzled byte offset within a tile of 128B rows (8 chunks of 16B)
__device__ __forceinline__ uint32_t tile_off(int row, int chunk) {
    return (uint32_t)(row * 128 + ((chunk ^ (row & 7)) << 4));
}

// =================== fp32 -> bf16 conversion =================================
__global__ __launch_bounds__(256)
void cvt_bf_kernel(const float* __restrict__ x, bf16* __restrict__ y, int n4)
{
    int i = blockIdx.x * blockDim.x + threadIdx.x;
    if (i >= n4) return;
    float4 v = ((const float4*)x)[i];
    ((bf162*)y)[2 * i]     = bf162(__float2bfloat16(v.x), __float2bfloat16(v.y));
    ((bf162*)y)[2 * i + 1] = bf162(__float2bfloat16(v.z), __float2bfloat16(v.w));
}

// =================== bf16 GEMM: Y[M,N] = A@W^T + bias ========================
// CTA 128x128, BK=64, 2-stage cp.async. 8 warps 4x2, warp tile 32x64.
// Templated output: bf16 (projections) or fp32 (O-projection).
#define BFG_STAGE 32768
#define BFG_SMEM  (2 * BFG_STAGE)

template <typename OutT>
__global__ __launch_bounds__(256)
void gemm_bf_kernel(const bf16* __restrict__ A, const bf16* __restrict__ W,
                    const float* __restrict__ bias, OutT* __restrict__ Yb)
{
    extern __shared__ char tsm[];
    const int tid = threadIdx.x;
    const int wid = tid >> 5;
    const int lane = tid & 31;
    const int wm = wid >> 1;
    const int wn = wid & 1;
    const int bm = blockIdx.y * 128;
    const int bn = blockIdx.x * 128;
    const uint32_t sbase = s2u(tsm);

    float acc[2][8][4];
#pragma unroll
    for (int i = 0; i < 2; i++)
#pragma unroll
        for (int j = 0; j < 8; j++)
#pragma unroll
            for (int r = 0; r < 4; r++) acc[i][j][r] = 0.f;

    auto load_stage = [&](int kt, int s) {
        const uint32_t stage = sbase + s * BFG_STAGE;
#pragma unroll
        for (int i = 0; i < 8; i++) {
            int u = tid + i * 256;
            int sub = u >> 10;
            int idx = u & 1023;
            int row = idx >> 3;
            int c = idx & 7;
            const bf16* src = sub ? W + (size_t)(bn + row) * DIM
                                  : A + (size_t)(bm + row) * DIM;
            cp16(stage + sub * 16384 + tile_off(row, c), src + kt * 64 + c * 8);
        }
        cp_commit();
    };

    load_stage(0, 0);
    for (int kt = 0; kt < 16; kt++) {
        if (kt < 15) { load_stage(kt + 1, (kt + 1) & 1); cp_wait<1>(); }
        else cp_wait<0>();
        __syncthreads();
        const uint32_t st = sbase + (kt & 1) * BFG_STAGE;
#pragma unroll
        for (int ks = 0; ks < 4; ks++) {
            uint32_t af[2][4];
#pragma unroll
            for (int mt = 0; mt < 2; mt++) {
                int row = wm * 32 + mt * 16 + (lane & 15);
                int chunk = ks * 2 + (lane >> 4);
                ldsm4(af[mt][0], af[mt][1], af[mt][2], af[mt][3],
                      st + tile_off(row, chunk));
            }
            uint32_t bfg[4][4];
#pragma unroll
            for (int p = 0; p < 4; p++) {
                int n = wn * 64 + p * 16 + ((lane >> 4) << 3) + (lane & 7);
                int chunk = ks * 2 + ((lane >> 3) & 1);
                ldsm4(bfg[p][0], bfg[p][1], bfg[p][2], bfg[p][3],
                      st + 16384 + tile_off(n, chunk));
            }
#pragma unroll
            for (int mt = 0; mt < 2; mt++)
#pragma unroll
                for (int nt = 0; nt < 8; nt++)
                    mma16816(acc[mt][nt], af[mt], &bfg[nt >> 1][(nt & 1) * 2]);
        }
        __syncthreads();
    }

    const int gq = lane >> 2;
    const int tq = lane & 3;
#pragma unroll
    for (int mt = 0; mt < 2; mt++)
#pragma unroll
        for (int nt = 0; nt < 8; nt++) {
            int col = bn + wn * 64 + nt * 8 + tq * 2;
            float bx = bias[col], by = bias[col + 1];
            int r0 = bm + wm * 32 + mt * 16 + gq;
            float v00 = acc[mt][nt][0] + bx, v01 = acc[mt][nt][1] + by;
            float v10 = acc[mt][nt][2] + bx, v11 = acc[mt][nt][3] + by;
            if (sizeof(OutT) == 2) {
                *(bf162*)((bf16*)Yb + (size_t)r0 * DIM + col) =
                    bf162(__float2bfloat16(v00), __float2bfloat16(v01));
                *(bf162*)((bf16*)Yb + (size_t)(r0 + 8) * DIM + col) =
                    bf162(__float2bfloat16(v10), __float2bfloat16(v11));
            } else {
                *(float2*)((float*)Yb + (size_t)r0 * DIM + col) =
                    make_float2(v00, v01);
                *(float2*)((float*)Yb + (size_t)(r0 + 8) * DIM + col) =
                    make_float2(v10, v11);
            }
        }
}

// =================== fused attention =========================================
// CTA = 64 q-rows of one (b,h). SMEM: scores 64x1024 bf16 as 16 swizzled
// 64x64 tiles (128KB) + q tile 8KB + k/v double buffer 2x8KB.
// Phase 1: scores = q.k^T/8 -> smem bf16
// Phase 2: double softmax, fp32 in registers (8 rows/warp)
// Phase 3: ctx = attn.v -> gmem bf16
#define FA_OFF_Q  131072
#define FA_OFF_KV 139264
#define FA_SMEM   (FA_OFF_KV + 2 * 8192)   // 155648

__global__ __launch_bounds__(256)
void fused_attn_kernel(const bf16* __restrict__ qb, const bf16* __restrict__ kb,
                       const bf16* __restrict__ vb, bf16* __restrict__ ctxb)
{
    extern __shared__ char fsm[];
    const int tid = threadIdx.x;
    const int wid = tid >> 5;
    const int lane = tid & 31;
    const int bh = blockIdx.y;
    const int b = bh >> 4;
    const int h = bh & 15;
    const int bm = blockIdx.x * 64;
    const uint32_t sbase = s2u(fsm);
    const int gq = lane >> 2;
    const int tq = lane & 3;

    const bf16* qp = qb + (size_t)(b * SEQ) * DIM + h * DK;
    const bf16* kp = kb + (size_t)(b * SEQ) * DIM + h * DK;
    const bf16* vp = vb + (size_t)(b * SEQ) * DIM + h * DK;

    // ---- load q tile (64 rows x 64 d) + k tile 0 ----
#pragma unroll
    for (int i = 0; i < 2; i++) {
        int u = tid + i * 256;
        int row = u >> 3, c = u & 7;
        cp16(sbase + FA_OFF_Q + tile_off(row, c),
             qp + (size_t)(bm + row) * DIM + c * 8);
    }
    auto load_k = [&](int kt, int s) {
#pragma unroll
        for (int i = 0; i < 2; i++) {
            int u = tid + i * 256;
            int row = u >> 3, c = u & 7;
            cp16(sbase + FA_OFF_KV + s * 8192 + tile_off(row, c),
                 kp + (size_t)(kt * 64 + row) * DIM + c * 8);
        }
        cp_commit();
    };
    auto load_v = [&](int kt, int s) {
#pragma unroll
        for (int i = 0; i < 2; i++) {
            int u = tid + i * 256;
            int row = u >> 3, c = u & 7;
            cp16(sbase + FA_OFF_KV + s * 8192 + tile_off(row, c),
                 vp + (size_t)(kt * 64 + row) * DIM + c * 8);
        }
        cp_commit();
    };
    load_k(0, 0);

    // ---- phase 1: scores ----
    // 8 warps = 2(m) x 4(n): warp tile 32q x 16keys per kt
    const int wm1 = wid >> 2;      // 0..1
    const int wn1 = wid & 3;       // 0..3
    for (int kt = 0; kt < 16; kt++) {
        if (kt < 15) { load_k(kt + 1, (kt + 1) & 1); cp_wait<1>(); }
        else cp_wait<0>();
        __syncthreads();
        const uint32_t st = sbase + FA_OFF_KV + (kt & 1) * 8192;

        float acc[2][2][4];
#pragma unroll
        for (int i = 0; i < 2; i++)
#pragma unroll
            for (int j = 0; j < 2; j++)
#pragma unroll
                for (int r = 0; r < 4; r++) acc[i][j][r] = 0.f;

#pragma unroll
        for (int ks = 0; ks < 4; ks++) {
            uint32_t aq[2][4];
#pragma unroll
            for (int mt = 0; mt < 2; mt++) {
                int row = wm1 * 32 + mt * 16 + (lane & 15);
                int chunk = ks * 2 + (lane >> 4);
                ldsm4(aq[mt][0], aq[mt][1], aq[mt][2], aq[mt][3],
                      sbase + FA_OFF_Q + tile_off(row, chunk));
            }
            uint32_t bk4[4];
            {
                int n = wn1 * 16 + ((lane >> 4) << 3) + (lane & 7);
                int chunk = ks * 2 + ((lane >> 3) & 1);
                ldsm4(bk4[0], bk4[1], bk4[2], bk4[3], st + tile_off(n, chunk));
            }
#pragma unroll
            for (int mt = 0; mt < 2; mt++)
#pragma unroll
                for (int nt = 0; nt < 2; nt++)
                    mma16816(acc[mt][nt], aq[mt], &bk4[nt * 2]);
        }
        // store scores * 0.125 into smem tile kt (bf16)
#pragma unroll
        for (int mt = 0; mt < 2; mt++)
#pragma unroll
            for (int nt = 0; nt < 2; nt++) {
                int col = wn1 * 16 + nt * 8 + tq * 2;
                int r0 = wm1 * 32 + mt * 16 + gq;
                uint32_t base = sbase + kt * 8192;
                *(bf162*)(fsm + (kt * 8192 + tile_off(r0, col >> 3) + (col & 7) * 2)) =
                    bf162(__float2bfloat16(acc[mt][nt][0] * 0.125f),
                          __float2bfloat16(acc[mt][nt][1] * 0.125f));
                *(bf162*)(fsm + (kt * 8192 + tile_off(r0 + 8, col >> 3) + (col & 7) * 2)) =
                    bf162(__float2bfloat16(acc[mt][nt][2] * 0.125f),
                          __float2bfloat16(acc[mt][nt][3] * 0.125f));
                (void)base;
            }
        __syncthreads();
    }

    // preload v0 (overlaps softmax)
    load_v(0, 0);

    // ---- phase 2: double softmax, 8 rows per warp, fp32 registers ----
#pragma unroll 1
    for (int rr = 0; rr < 8; rr++) {
        int row = wid * 8 + rr;
        float vals[32];
#pragma unroll
        for (int j = 0; j < 4; j++) {
            int ch = lane * 4 + j;            // 0..127 chunk of 8 cols
            uint4 u4 = *(uint4*)(fsm + ((ch >> 3) * 8192 + tile_off(row, ch & 7)));
            const bf162* pv = (const bf162*)&u4;
#pragma unroll
            for (int t = 0; t < 4; t++) {
                vals[j * 8 + 2 * t]     = __bfloat162float(pv[t].x);
                vals[j * 8 + 2 * t + 1] = __bfloat162float(pv[t].y);
            }
        }
#pragma unroll
        for (int pass = 0; pass < 2; pass++) {
            float m = vals[0];
#pragma unroll
            for (int i = 1; i < 32; i++) m = fmaxf(m, vals[i]);
#pragma unroll
            for (int off = 16; off > 0; off >>= 1)
                m = fmaxf(m, __shfl_xor_sync(0xffffffffu, m, off));
            float sum = 0.f;
#pragma unroll
            for (int i = 0; i < 32; i++) {
                vals[i] = __expf(vals[i] - m);
                sum += vals[i];
            }
#pragma unroll
            for (int off = 16; off > 0; off >>= 1)
                sum += __shfl_xor_sync(0xffffffffu, sum, off);
            float inv = 1.0f / sum;
#pragma unroll
            for (int i = 0; i < 32; i++) vals[i] *= inv;
        }
        // write back bf16
#pragma unroll
        for (int j = 0; j < 4; j++) {
            int ch = lane * 4 + j;
            uint4 u4;
            bf162* pv = (bf162*)&u4;
#pragma unroll
            for (int t = 0; t < 4; t++)
                pv[t] = bf162(__float2bfloat16(vals[j * 8 + 2 * t]),
                              __float2bfloat16(vals[j * 8 + 2 * t + 1]));
            *(uint4*)(fsm + ((ch >> 3) * 8192 + tile_off(row, ch & 7))) = u4;
        }
    }
    cp_wait<0>();
    __syncthreads();

    // ---- phase 3: ctx = attn . v ----
    // 8 warps = 4(m) x 2(n): warp tile 16q x 32d
    const int wm3 = wid >> 1;     // 0..3
    const int wn3 = wid & 1;      // 0..1
    float acc3[4][4];
#pragma unroll
    for (int j = 0; j < 4; j++)
#pragma unroll
        for (int r = 0; r < 4; r++) acc3[j][r] = 0.f;

    for (int kt = 0; kt < 16; kt++) {
        if (kt < 15) { load_v(kt + 1, (kt + 1) & 1); cp_wait<1>(); }
        else cp_wait<0>();
        __syncthreads();
        const uint32_t st = sbase + FA_OFF_KV + (kt & 1) * 8192;
#pragma unroll
        for (int ks = 0; ks < 4; ks++) {
            uint32_t aA[4];
            {
                int row = wm3 * 16 + (lane & 15);
                int chunk = ks * 2 + (lane >> 4);
                ldsm4(aA[0], aA[1], aA[2], aA[3],
                      sbase + kt * 8192 + tile_off(row, chunk));
            }
            uint32_t bv4[2][4];
#pragma unroll
            for (int p = 0; p < 2; p++) {
                int mat = lane >> 3;
                int l = lane & 7;
                int srow = ks * 16 + ((mat & 1) << 3) + l;
                int dchunk = wn3 * 4 + p * 2 + (mat >> 1);
                ldsm4t(bv4[p][0], bv4[p][1], bv4[p][2], bv4[p][3],
                       st + tile_off(srow, dchunk));
            }
#pragma unroll
            for (int nt = 0; nt < 4; nt++)
                mma16816(acc3[nt], aA, &bv4[nt >> 1][(nt & 1) * 2]);
        }
        __syncthreads();
    }

    // epilogue: ctx bf16
#pragma unroll
    for (int nt = 0; nt < 4; nt++) {
        int col = wn3 * 32 + nt * 8 + tq * 2;
#pragma unroll
        for (int half = 0; half < 2; half++) {
            int r = bm + wm3 * 16 + half * 8 + gq;
            size_t off = (size_t)(b * SEQ + r) * DIM + h * DK + col;
            *(bf162*)(ctxb + off) =
                bf162(__float2bfloat16(acc3[nt][half * 2]),
                      __float2bfloat16(acc3[nt][half * 2 + 1]));
        }
    }
}

// ---------------- residual + layernorm --------------------------------------
__global__ __launch_bounds__(256)
void ln_kernel(const float* __restrict__ proj, const float* __restrict__ Qres,
               const float* __restrict__ g, const float* __restrict__ bta,
               float* __restrict__ out)
{
    __shared__ float red[256];
    const size_t row = blockIdx.x;
    const float* x1 = proj + row * DIM;
    const float* x2 = Qres + row * DIM;
    const int tid = threadIdx.x;

    float vals[4];
    float sum = 0.f;
#pragma unroll
    for (int j = 0; j < 4; j++) {
        int i = tid + j * 256;
        vals[j] = x1[i] + x2[i];
        sum += vals[j];
    }
    red[tid] = sum; __syncthreads();
    for (int s = 128; s > 0; s >>= 1) {
        if (tid < s) red[tid] += red[tid + s];
        __syncthreads();
    }
    float mu = red[0] / DIM; __syncthreads();

    float sq = 0.f;
#pragma unroll
    for (int j = 0; j < 4; j++) {
        float d = vals[j] - mu;
        sq += d * d;
    }
    red[tid] = sq; __syncthreads();
    for (int s = 128; s > 0; s >>= 1) {
        if (tid < s) red[tid] += red[tid + s];
        __syncthreads();
    }
    float rstd = rsqrtf(red[0] / DIM + LN_EPS);

    float* op = out + row * DIM;
#pragma unroll
    for (int j = 0; j < 4; j++) {
        int i = tid + j * 256;
        op[i] = (vals[j] - mu) * rstd * g[i] + bta[i];
    }
}

// ---------------- launch -----------------------------------------------------
extern "C" void kernel_launch(void* const* d_in, const int* in_sizes, int n_in,
                              void* d_out, int out_size)
{
    const float* Q   = (const float*)d_in[0];
    const float* K   = (const float*)d_in[1];
    const float* V   = (const float*)d_in[2];
    const float* Wq  = (const float*)d_in[3];
    const float* bq  = (const float*)d_in[4];
    const float* Wk  = (const float*)d_in[5];
    const float* bk  = (const float*)d_in[6];
    const float* Wv  = (const float*)d_in[7];
    const float* bv  = (const float*)d_in[8];
    const float* Wo  = (const float*)d_in[9];
    const float* bo  = (const float*)d_in[10];
    const float* lng = (const float*)d_in[11];
    const float* lnb = (const float*)d_in[12];
    float* out = (float*)d_out;

    bf16 *inb, *qbp, *kbp, *vbp, *ctxb, *wb;
    float* outb;
    cudaGetSymbolAddress((void**)&inb,  g_inb);
    cudaGetSymbolAddress((void**)&qbp,  g_qb);
    cudaGetSymbolAddress((void**)&kbp,  g_kb);
    cudaGetSymbolAddress((void**)&vbp,  g_vb);
    cudaGetSymbolAddress((void**)&ctxb, g_ctxb);
    cudaGetSymbolAddress((void**)&wb,   g_wb);
    cudaGetSymbolAddress((void**)&outb, g_outb);

    cudaFuncSetAttribute(gemm_bf_kernel<bf16>,
                         cudaFuncAttributeMaxDynamicSharedMemorySize, BFG_SMEM);
    cudaFuncSetAttribute(gemm_bf_kernel<float>,
                         cudaFuncAttributeMaxDynamicSharedMemorySize, BFG_SMEM);
    cudaFuncSetAttribute(fused_attn_kernel,
                         cudaFuncAttributeMaxDynamicSharedMemorySize, FA_SMEM);

    const int n4_in = MROWS * DIM / 4;
    const int n4_w  = DIM * DIM / 4;
    dim3 ggemm(DIM / 128, MROWS / 128);   // (8, 32)

    // Q/K/V projections (bf16)
    cvt_bf_kernel<<<n4_in / 256, 256>>>(Q, inb, n4_in);
    cvt_bf_kernel<<<n4_w / 256, 256>>>(Wq, wb, n4_w);
    gemm_bf_kernel<bf16><<<ggemm, 256, BFG_SMEM>>>(inb, wb, bq, qbp);

    cvt_bf_kernel<<<n4_in / 256, 256>>>(K, inb, n4_in);
    cvt_bf_kernel<<<n4_w / 256, 256>>>(Wk, wb, n4_w);
    gemm_bf_kernel<bf16><<<ggemm, 256, BFG_SMEM>>>(inb, wb, bk, kbp);

    cvt_bf_kernel<<<n4_in / 256, 256>>>(V, inb, n4_in);
    cvt_bf_kernel<<<n4_w / 256, 256>>>(Wv, wb, n4_w);
    gemm_bf_kernel<bf16><<<ggemm, 256, BFG_SMEM>>>(inb, wb, bv, vbp);

    // fused attention: scores + double softmax + ctx
    dim3 gfa(SEQ / 64, BATCH * NHEAD);    // (16, 64)
    fused_attn_kernel<<<gfa, 256, FA_SMEM>>>(qbp, kbp, vbp, ctxb);

    // O-projection (bf16, fp32 out)
    cvt_bf_kernel<<<n4_w / 256, 256>>>(Wo, wb, n4_w);
    gemm_bf_kernel<float><<<ggemm, 256, BFG_SMEM>>>(ctxb, wb, bo, outb);

    ln_kernel<<<MROWS, 256>>>(outb, Q, lng, lnb, out);
}

// round 6
// speedup vs baseline: 7.0480x; 1.0049x over previous
#include <cuda_runtime.h>
#include <cuda_bf16.h>
#include <cstdint>
#include <math.h>

// Problem constants
#define BATCH 4
#define SEQ   1024
#define DIM   1024
#define NHEAD 16
#define DK    64
#define MROWS (BATCH * SEQ)   // 4096
#define LN_EPS 1e-5f

typedef __nv_bfloat16 bf16;
typedef __nv_bfloat162 bf162;

// ---------------- scratch (device globals: no allocs allowed) ----------------
__device__ bf16 g_qin[(size_t)MROWS * DIM];
__device__ bf16 g_kin[(size_t)MROWS * DIM];
__device__ bf16 g_vin[(size_t)MROWS * DIM];
__device__ bf16 g_qb[(size_t)MROWS * DIM];
__device__ bf16 g_kb[(size_t)MROWS * DIM];
__device__ bf16 g_vb[(size_t)MROWS * DIM];
__device__ bf16 g_ctxb[(size_t)MROWS * DIM];
__device__ bf16 g_wq[(size_t)DIM * DIM];
__device__ bf16 g_wk[(size_t)DIM * DIM];
__device__ bf16 g_wv[(size_t)DIM * DIM];
__device__ bf16 g_wo[(size_t)DIM * DIM];
__device__ float g_outb[(size_t)MROWS * DIM];

// =================== baseline-PTX helpers ====================================
__device__ __forceinline__ uint32_t s2u(const void* p) {
    uint32_t a;
    asm("{ .reg .u64 t; cvta.to.shared.u64 t, %1; cvt.u32.u64 %0, t; }"
        : "=r"(a) : "l"(p));
    return a;
}
__device__ __forceinline__ void cp16(uint32_t dst, const void* src) {
    asm volatile("cp.async.cg.shared.global [%0], [%1], 16;"
                 :: "r"(dst), "l"(src) : "memory");
}
__device__ __forceinline__ void cp_commit() {
    asm volatile("cp.async.commit_group;" ::: "memory");
}
template <int N>
__device__ __forceinline__ void cp_wait() {
    asm volatile("cp.async.wait_group %0;" :: "n"(N) : "memory");
}
__device__ __forceinline__ void ldsm4(uint32_t& r0, uint32_t& r1,
                                      uint32_t& r2, uint32_t& r3, uint32_t a) {
    asm volatile("ldmatrix.sync.aligned.m8n8.x4.shared.b16 {%0,%1,%2,%3}, [%4];"
                 : "=r"(r0), "=r"(r1), "=r"(r2), "=r"(r3) : "r"(a));
}
__device__ __forceinline__ void ldsm4t(uint32_t& r0, uint32_t& r1,
                                       uint32_t& r2, uint32_t& r3, uint32_t a) {
    asm volatile("ldmatrix.sync.aligned.m8n8.x4.trans.shared.b16 {%0,%1,%2,%3}, [%4];"
                 : "=r"(r0), "=r"(r1), "=r"(r2), "=r"(r3) : "r"(a));
}
__device__ __forceinline__ void mma16816(float* c, const uint32_t* a,
                                         const uint32_t* b) {
    asm volatile("mma.sync.aligned.m16n8k16.row.col.f32.bf16.bf16.f32 "
                 "{%0,%1,%2,%3}, {%4,%5,%6,%7}, {%8,%9}, {%0,%1,%2,%3};"
                 : "+f"(c[0]), "+f"(c[1]), "+f"(c[2]), "+f"(c[3])
                 : "r"(a[0]), "r"(a[1]), "r"(a[2]), "r"(a[3]),
                   "r"(b[0]), "r"(b[1]));
}
// swizzled byte offset within a tile of 128B rows (8 chunks of 16B)
__device__ __forceinline__ uint32_t tile_off(int row, int chunk) {
    return (uint32_t)(row * 128 + ((chunk ^ (row & 7)) << 4));
}

// =================== batched fp32 -> bf16 conversion =========================
struct CvtJobs {
    const float* src[7];
    bf16* dst[7];
    int n4[7];
};

__global__ __launch_bounds__(256)
void cvt_all_kernel(CvtJobs jobs)
{
    const int j = blockIdx.y;
    int i = blockIdx.x * blockDim.x + threadIdx.x;
    if (i >= jobs.n4[j]) return;
    const float* x = jobs.src[j];
    bf16* y = jobs.dst[j];
    float4 v = ((const float4*)x)[i];
    ((bf162*)y)[2 * i]     = bf162(__float2bfloat16(v.x), __float2bfloat16(v.y));
    ((bf162*)y)[2 * i + 1] = bf162(__float2bfloat16(v.z), __float2bfloat16(v.w));
}

// =================== bf16 GEMM core (shared by QKV and O) ====================
// CTA 128x128, BK=64, 2-stage cp.async. 8 warps 4x2, warp tile 32x64.
#define BFG_STAGE 32768
#define BFG_SMEM  (2 * BFG_STAGE)

template <typename OutT>
__device__ __forceinline__
void gemm_body(const bf16* __restrict__ A, const bf16* __restrict__ W,
               const float* __restrict__ bias, OutT* __restrict__ Yb,
               char* tsm)
{
    const int tid = threadIdx.x;
    const int wid = tid >> 5;
    const int lane = tid & 31;
    const int wm = wid >> 1;
    const int wn = wid & 1;
    const int bm = blockIdx.y * 128;
    const int bn = blockIdx.x * 128;
    const uint32_t sbase = s2u(tsm);

    float acc[2][8][4];
#pragma unroll
    for (int i = 0; i < 2; i++)
#pragma unroll
        for (int j = 0; j < 8; j++)
#pragma unroll
            for (int r = 0; r < 4; r++) acc[i][j][r] = 0.f;

    auto load_stage = [&](int kt, int s) {
        const uint32_t stage = sbase + s * BFG_STAGE;
#pragma unroll
        for (int i = 0; i < 8; i++) {
            int u = tid + i * 256;
            int sub = u >> 10;
            int idx = u & 1023;
            int row = idx >> 3;
            int c = idx & 7;
            const bf16* src = sub ? W + (size_t)(bn + row) * DIM
                                  : A + (size_t)(bm + row) * DIM;
            cp16(stage + sub * 16384 + tile_off(row, c), src + kt * 64 + c * 8);
        }
        cp_commit();
    };

    load_stage(0, 0);
    for (int kt = 0; kt < 16; kt++) {
        if (kt < 15) { load_stage(kt + 1, (kt + 1) & 1); cp_wait<1>(); }
        else cp_wait<0>();
        __syncthreads();
        const uint32_t st = sbase + (kt & 1) * BFG_STAGE;
#pragma unroll
        for (int ks = 0; ks < 4; ks++) {
            uint32_t af[2][4];
#pragma unroll
            for (int mt = 0; mt < 2; mt++) {
                int row = wm * 32 + mt * 16 + (lane & 15);
                int chunk = ks * 2 + (lane >> 4);
                ldsm4(af[mt][0], af[mt][1], af[mt][2], af[mt][3],
                      st + tile_off(row, chunk));
            }
            uint32_t bfg[4][4];
#pragma unroll
            for (int p = 0; p < 4; p++) {
                int n = wn * 64 + p * 16 + ((lane >> 4) << 3) + (lane & 7);
                int chunk = ks * 2 + ((lane >> 3) & 1);
                ldsm4(bfg[p][0], bfg[p][1], bfg[p][2], bfg[p][3],
                      st + 16384 + tile_off(n, chunk));
            }
#pragma unroll
            for (int mt = 0; mt < 2; mt++)
#pragma unroll
                for (int nt = 0; nt < 8; nt++)
                    mma16816(acc[mt][nt], af[mt], &bfg[nt >> 1][(nt & 1) * 2]);
        }
        __syncthreads();
    }

    const int gq = lane >> 2;
    const int tq = lane & 3;
#pragma unroll
    for (int mt = 0; mt < 2; mt++)
#pragma unroll
        for (int nt = 0; nt < 8; nt++) {
            int col = bn + wn * 64 + nt * 8 + tq * 2;
            float bx = bias[col], by = bias[col + 1];
            int r0 = bm + wm * 32 + mt * 16 + gq;
            float v00 = acc[mt][nt][0] + bx, v01 = acc[mt][nt][1] + by;
            float v10 = acc[mt][nt][2] + bx, v11 = acc[mt][nt][3] + by;
            if (sizeof(OutT) == 2) {
                *(bf162*)((bf16*)Yb + (size_t)r0 * DIM + col) =
                    bf162(__float2bfloat16(v00), __float2bfloat16(v01));
                *(bf162*)((bf16*)Yb + (size_t)(r0 + 8) * DIM + col) =
                    bf162(__float2bfloat16(v10), __float2bfloat16(v11));
            } else {
                *(float2*)((float*)Yb + (size_t)r0 * DIM + col) =
                    make_float2(v00, v01);
                *(float2*)((float*)Yb + (size_t)(r0 + 8) * DIM + col) =
                    make_float2(v10, v11);
            }
        }
}

// merged Q/K/V projection: blockIdx.z selects the (input, weight, bias, out) set
__global__ __launch_bounds__(256)
void gemm_qkv_kernel(const bf16* A0, const bf16* A1, const bf16* A2,
                     const bf16* W0, const bf16* W1, const bf16* W2,
                     const float* b0, const float* b1, const float* b2,
                     bf16* Y0, bf16* Y1, bf16* Y2)
{
    extern __shared__ char tsm[];
    const int z = blockIdx.z;
    const bf16* A = (z == 0) ? A0 : (z == 1) ? A1 : A2;
    const bf16* W = (z == 0) ? W0 : (z == 1) ? W1 : W2;
    const float* bias = (z == 0) ? b0 : (z == 1) ? b1 : b2;
    bf16* Y = (z == 0) ? Y0 : (z == 1) ? Y1 : Y2;
    gemm_body<bf16>(A, W, bias, Y, tsm);
}

__global__ __launch_bounds__(256)
void gemm_o_kernel(const bf16* __restrict__ A, const bf16* __restrict__ W,
                   const float* __restrict__ bias, float* __restrict__ Y)
{
    extern __shared__ char tsm[];
    gemm_body<float>(A, W, bias, Y, tsm);
}

// =================== fused attention =========================================
// CTA = 64 q-rows of one (b,h). SMEM: scores 64x1024 bf16 as 16 swizzled
// 64x64 tiles (128KB) + q tile 8KB + k/v double buffer 2x8KB.
#define FA_OFF_Q  131072
#define FA_OFF_KV 139264
#define FA_SMEM   (FA_OFF_KV + 2 * 8192)   // 155648

__global__ __launch_bounds__(256)
void fused_attn_kernel(const bf16* __restrict__ qb, const bf16* __restrict__ kb,
                       const bf16* __restrict__ vb, bf16* __restrict__ ctxb)
{
    extern __shared__ char fsm[];
    const int tid = threadIdx.x;
    const int wid = tid >> 5;
    const int lane = tid & 31;
    const int bh = blockIdx.y;
    const int b = bh >> 4;
    const int h = bh & 15;
    const int bm = blockIdx.x * 64;
    const uint32_t sbase = s2u(fsm);
    const int gq = lane >> 2;
    const int tq = lane & 3;

    const bf16* qp = qb + (size_t)(b * SEQ) * DIM + h * DK;
    const bf16* kp = kb + (size_t)(b * SEQ) * DIM + h * DK;
    const bf16* vp = vb + (size_t)(b * SEQ) * DIM + h * DK;

#pragma unroll
    for (int i = 0; i < 2; i++) {
        int u = tid + i * 256;
        int row = u >> 3, c = u & 7;
        cp16(sbase + FA_OFF_Q + tile_off(row, c),
             qp + (size_t)(bm + row) * DIM + c * 8);
    }
    auto load_k = [&](int kt, int s) {
#pragma unroll
        for (int i = 0; i < 2; i++) {
            int u = tid + i * 256;
            int row = u >> 3, c = u & 7;
            cp16(sbase + FA_OFF_KV + s * 8192 + tile_off(row, c),
                 kp + (size_t)(kt * 64 + row) * DIM + c * 8);
        }
        cp_commit();
    };
    auto load_v = [&](int kt, int s) {
#pragma unroll
        for (int i = 0; i < 2; i++) {
            int u = tid + i * 256;
            int row = u >> 3, c = u & 7;
            cp16(sbase + FA_OFF_KV + s * 8192 + tile_off(row, c),
                 vp + (size_t)(kt * 64 + row) * DIM + c * 8);
        }
        cp_commit();
    };
    load_k(0, 0);

    // ---- phase 1: scores ----
    const int wm1 = wid >> 2;
    const int wn1 = wid & 3;
    for (int kt = 0; kt < 16; kt++) {
        if (kt < 15) { load_k(kt + 1, (kt + 1) & 1); cp_wait<1>(); }
        else cp_wait<0>();
        __syncthreads();
        const uint32_t st = sbase + FA_OFF_KV + (kt & 1) * 8192;

        float acc[2][2][4];
#pragma unroll
        for (int i = 0; i < 2; i++)
#pragma unroll
            for (int j = 0; j < 2; j++)
#pragma unroll
                for (int r = 0; r < 4; r++) acc[i][j][r] = 0.f;

#pragma unroll
        for (int ks = 0; ks < 4; ks++) {
            uint32_t aq[2][4];
#pragma unroll
            for (int mt = 0; mt < 2; mt++) {
                int row = wm1 * 32 + mt * 16 + (lane & 15);
                int chunk = ks * 2 + (lane >> 4);
                ldsm4(aq[mt][0], aq[mt][1], aq[mt][2], aq[mt][3],
                      sbase + FA_OFF_Q + tile_off(row, chunk));
            }
            uint32_t bk4[4];
            {
                int n = wn1 * 16 + ((lane >> 4) << 3) + (lane & 7);
                int chunk = ks * 2 + ((lane >> 3) & 1);
                ldsm4(bk4[0], bk4[1], bk4[2], bk4[3], st + tile_off(n, chunk));
            }
#pragma unroll
            for (int mt = 0; mt < 2; mt++)
#pragma unroll
                for (int nt = 0; nt < 2; nt++)
                    mma16816(acc[mt][nt], aq[mt], &bk4[nt * 2]);
        }
#pragma unroll
        for (int mt = 0; mt < 2; mt++)
#pragma unroll
            for (int nt = 0; nt < 2; nt++) {
                int col = wn1 * 16 + nt * 8 + tq * 2;
                int r0 = wm1 * 32 + mt * 16 + gq;
                *(bf162*)(fsm + (kt * 8192 + tile_off(r0, col >> 3) + (col & 7) * 2)) =
                    bf162(__float2bfloat16(acc[mt][nt][0] * 0.125f),
                          __float2bfloat16(acc[mt][nt][1] * 0.125f));
                *(bf162*)(fsm + (kt * 8192 + tile_off(r0 + 8, col >> 3) + (col & 7) * 2)) =
                    bf162(__float2bfloat16(acc[mt][nt][2] * 0.125f),
                          __float2bfloat16(acc[mt][nt][3] * 0.125f));
            }
        __syncthreads();
    }

    load_v(0, 0);

    // ---- phase 2: double softmax, 8 rows per warp, fp32 registers ----
#pragma unroll 1
    for (int rr = 0; rr < 8; rr++) {
        int row = wid * 8 + rr;
        float vals[32];
#pragma unroll
        for (int j = 0; j < 4; j++) {
            int ch = lane * 4 + j;
            uint4 u4 = *(uint4*)(fsm + ((ch >> 3) * 8192 + tile_off(row, ch & 7)));
            const bf162* pv = (const bf162*)&u4;
#pragma unroll
            for (int t = 0; t < 4; t++) {
                vals[j * 8 + 2 * t]     = __bfloat162float(pv[t].x);
                vals[j * 8 + 2 * t + 1] = __bfloat162float(pv[t].y);
            }
        }
#pragma unroll
        for (int pass = 0; pass < 2; pass++) {
            float m = vals[0];
#pragma unroll
            for (int i = 1; i < 32; i++) m = fmaxf(m, vals[i]);
#pragma unroll
            for (int off = 16; off > 0; off >>= 1)
                m = fmaxf(m, __shfl_xor_sync(0xffffffffu, m, off));
            float sum = 0.f;
#pragma unroll
            for (int i = 0; i < 32; i++) {
                vals[i] = __expf(vals[i] - m);
                sum += vals[i];
            }
#pragma unroll
            for (int off = 16; off > 0; off >>= 1)
                sum += __shfl_xor_sync(0xffffffffu, sum, off);
            float inv = 1.0f / sum;
#pragma unroll
            for (int i = 0; i < 32; i++) vals[i] *= inv;
        }
#pragma unroll
        for (int j = 0; j < 4; j++) {
            int ch = lane * 4 + j;
            uint4 u4;
            bf162* pv = (bf162*)&u4;
#pragma unroll
            for (int t = 0; t < 4; t++)
                pv[t] = bf162(__float2bfloat16(vals[j * 8 + 2 * t]),
                              __float2bfloat16(vals[j * 8 + 2 * t + 1]));
            *(uint4*)(fsm + ((ch >> 3) * 8192 + tile_off(row, ch & 7))) = u4;
        }
    }
    cp_wait<0>();
    __syncthreads();

    // ---- phase 3: ctx = attn . v ----
    const int wm3 = wid >> 1;
    const int wn3 = wid & 1;
    float acc3[4][4];
#pragma unroll
    for (int j = 0; j < 4; j++)
#pragma unroll
        for (int r = 0; r < 4; r++) acc3[j][r] = 0.f;

    for (int kt = 0; kt < 16; kt++) {
        if (kt < 15) { load_v(kt + 1, (kt + 1) & 1); cp_wait<1>(); }
        else cp_wait<0>();
        __syncthreads();
        const uint32_t st = sbase + FA_OFF_KV + (kt & 1) * 8192;
#pragma unroll
        for (int ks = 0; ks < 4; ks++) {
            uint32_t aA[4];
            {
                int row = wm3 * 16 + (lane & 15);
                int chunk = ks * 2 + (lane >> 4);
                ldsm4(aA[0], aA[1], aA[2], aA[3],
                      sbase + kt * 8192 + tile_off(row, chunk));
            }
            uint32_t bv4[2][4];
#pragma unroll
            for (int p = 0; p < 2; p++) {
                int mat = lane >> 3;
                int l = lane & 7;
                int srow = ks * 16 + ((mat & 1) << 3) + l;
                int dchunk = wn3 * 4 + p * 2 + (mat >> 1);
                ldsm4t(bv4[p][0], bv4[p][1], bv4[p][2], bv4[p][3],
                       st + tile_off(srow, dchunk));
            }
#pragma unroll
            for (int nt = 0; nt < 4; nt++)
                mma16816(acc3[nt], aA, &bv4[nt >> 1][(nt & 1) * 2]);
        }
        __syncthreads();
    }

#pragma unroll
    for (int nt = 0; nt < 4; nt++) {
        int col = wn3 * 32 + nt * 8 + tq * 2;
#pragma unroll
        for (int half = 0; half < 2; half++) {
            int r = bm + wm3 * 16 + half * 8 + gq;
            size_t off = (size_t)(b * SEQ + r) * DIM + h * DK + col;
            *(bf162*)(ctxb + off) =
                bf162(__float2bfloat16(acc3[nt][half * 2]),
                      __float2bfloat16(acc3[nt][half * 2 + 1]));
        }
    }
}

// ---------------- residual + layernorm --------------------------------------
__global__ __launch_bounds__(256)
void ln_kernel(const float* __restrict__ proj, const float* __restrict__ Qres,
               const float* __restrict__ g, const float* __restrict__ bta,
               float* __restrict__ out)
{
    __shared__ float red[256];
    const size_t row = blockIdx.x;
    const float* x1 = proj + row * DIM;
    const float* x2 = Qres + row * DIM;
    const int tid = threadIdx.x;

    float vals[4];
    float sum = 0.f;
#pragma unroll
    for (int j = 0; j < 4; j++) {
        int i = tid + j * 256;
        vals[j] = x1[i] + x2[i];
        sum += vals[j];
    }
    red[tid] = sum; __syncthreads();
    for (int s = 128; s > 0; s >>= 1) {
        if (tid < s) red[tid] += red[tid + s];
        __syncthreads();
    }
    float mu = red[0] / DIM; __syncthreads();

    float sq = 0.f;
#pragma unroll
    for (int j = 0; j < 4; j++) {
        float d = vals[j] - mu;
        sq += d * d;
    }
    red[tid] = sq; __syncthreads();
    for (int s = 128; s > 0; s >>= 1) {
        if (tid < s) red[tid] += red[tid + s];
        __syncthreads();
    }
    float rstd = rsqrtf(red[0] / DIM + LN_EPS);

    float* op = out + row * DIM;
#pragma unroll
    for (int j = 0; j < 4; j++) {
        int i = tid + j * 256;
        op[i] = (vals[j] - mu) * rstd * g[i] + bta[i];
    }
}

// ---------------- launch -----------------------------------------------------
extern "C" void kernel_launch(void* const* d_in, const int* in_sizes, int n_in,
                              void* d_out, int out_size)
{
    const float* Q   = (const float*)d_in[0];
    const float* K   = (const float*)d_in[1];
    const float* V   = (const float*)d_in[2];
    const float* Wq  = (const float*)d_in[3];
    const float* bq  = (const float*)d_in[4];
    const float* Wk  = (const float*)d_in[5];
    const float* bk  = (const float*)d_in[6];
    const float* Wv  = (const float*)d_in[7];
    const float* bv  = (const float*)d_in[8];
    const float* Wo  = (const float*)d_in[9];
    const float* bo  = (const float*)d_in[10];
    const float* lng = (const float*)d_in[11];
    const float* lnb = (const float*)d_in[12];
    float* out = (float*)d_out;

    bf16 *qin, *kin, *vin, *qbp, *kbp, *vbp, *ctxb, *wq, *wk, *wv, *wo;
    float* outb;
    cudaGetSymbolAddress((void**)&qin,  g_qin);
    cudaGetSymbolAddress((void**)&kin,  g_kin);
    cudaGetSymbolAddress((void**)&vin,  g_vin);
    cudaGetSymbolAddress((void**)&qbp,  g_qb);
    cudaGetSymbolAddress((void**)&kbp,  g_kb);
    cudaGetSymbolAddress((void**)&vbp,  g_vb);
    cudaGetSymbolAddress((void**)&ctxb, g_ctxb);
    cudaGetSymbolAddress((void**)&wq,   g_wq);
    cudaGetSymbolAddress((void**)&wk,   g_wk);
    cudaGetSymbolAddress((void**)&wv,   g_wv);
    cudaGetSymbolAddress((void**)&wo,   g_wo);
    cudaGetSymbolAddress((void**)&outb, g_outb);

    cudaFuncSetAttribute(gemm_qkv_kernel,
                         cudaFuncAttributeMaxDynamicSharedMemorySize, BFG_SMEM);
    cudaFuncSetAttribute(gemm_o_kernel,
                         cudaFuncAttributeMaxDynamicSharedMemorySize, BFG_SMEM);
    cudaFuncSetAttribute(fused_attn_kernel,
                         cudaFuncAttributeMaxDynamicSharedMemorySize, FA_SMEM);

    const int n4_in = MROWS * DIM / 4;   // 1M
    const int n4_w  = DIM * DIM / 4;     // 256K

    // one batched conversion launch: Q, K, V, Wq, Wk, Wv, Wo
    CvtJobs jobs;
    jobs.src[0] = Q;  jobs.dst[0] = qin; jobs.n4[0] = n4_in;
    jobs.src[1] = K;  jobs.dst[1] = kin; jobs.n4[1] = n4_in;
    jobs.src[2] = V;  jobs.dst[2] = vin; jobs.n4[2] = n4_in;
    jobs.src[3] = Wq; jobs.dst[3] = wq;  jobs.n4[3] = n4_w;
    jobs.src[4] = Wk; jobs.dst[4] = wk;  jobs.n4[4] = n4_w;
    jobs.src[5] = Wv; jobs.dst[5] = wv;  jobs.n4[5] = n4_w;
    jobs.src[6] = Wo; jobs.dst[6] = wo;  jobs.n4[6] = n4_w;
    cvt_all_kernel<<<dim3(n4_in / 256, 7), 256>>>(jobs);

    // merged Q/K/V projections
    dim3 gqkv(DIM / 128, MROWS / 128, 3);   // (8, 32, 3)
    gemm_qkv_kernel<<<gqkv, 256, BFG_SMEM>>>(qin, kin, vin, wq, wk, wv,
                                             bq, bk, bv, qbp, kbp, vbp);

    // fused attention: scores + double softmax + ctx
    dim3 gfa(SEQ / 64, BATCH * NHEAD);      // (16, 64)
    fused_attn_kernel<<<gfa, 256, FA_SMEM>>>(qbp, kbp, vbp, ctxb);

    // O-projection (bf16 in, fp32 out)
    dim3 ggemm(DIM / 128, MROWS / 128);     // (8, 32)
    gemm_o_kernel<<<ggemm, 256, BFG_SMEM>>>(ctxb, wo, bo, outb);

    ln_kernel<<<MROWS, 256>>>(outb, Q, lng, lnb, out);
}